// round 3
// baseline (speedup 1.0000x reference)
#include <cuda_runtime.h>
#include <cuda_bf16.h>
#include <math.h>
#include <stdint.h>

// Problem constants
#define Bq   4
#define Lq   2048
#define DMq  256
#define Hq   8
#define Eq   32
#define NLq  3
#define INTERq 16
#define Uq   40          // FACTOR*ceil(ln(2048)) = 40, same for u
#define BLq  (Bq*Lq)     // 8192

// ---------------- scratch (device globals; no allocation allowed) -------------
__device__ float g_x[BLq*DMq];
__device__ float g_q[BLq*DMq];
__device__ float g_k[BLq*DMq];
__device__ float g_v[BLq*DMq];
__device__ float g_ctx[BLq*DMq];
__device__ float g_tmp[BLq*DMq];
__device__ int   g_idx[Lq*Uq];
__device__ float g_M[Bq*Hq*Lq];
__device__ int   g_top[Bq*Hq*Uq];
__device__ float g_vmean[Bq*DMq];
__device__ float g_upd[Bq*Hq*Uq*Eq];
__device__ float g_bnp1[32*DMq];
__device__ float g_bnp2[32*DMq];
__device__ float g_bnm[DMq];
__device__ float g_bnv[DMq];

// ---------------- Threefry-2x32 (matches JAX) ---------------------------------
__host__ __device__ inline void tf2x32(uint32_t k0, uint32_t k1,
                                       uint32_t x0, uint32_t x1,
                                       uint32_t& o0, uint32_t& o1) {
    uint32_t ks[3];
    ks[0] = k0; ks[1] = k1; ks[2] = k0 ^ k1 ^ 0x1BD11BDAu;
    x0 += ks[0]; x1 += ks[1];
    const int R0[4] = {13, 15, 26, 6};
    const int R1[4] = {17, 29, 16, 24};
    #pragma unroll
    for (int i = 0; i < 5; i++) {
        #pragma unroll
        for (int j = 0; j < 4; j++) {
            int r = (i & 1) ? R1[j] : R0[j];
            x0 += x1;
            x1 = (x1 << r) | (x1 >> (32 - r));
            x1 ^= x0;
        }
        x0 += ks[(i + 1) % 3];
        x1 += ks[(i + 2) % 3] + (uint32_t)(i + 1);
    }
    o0 = x0; o1 = x1;
}

// JAX randint(rkey, (L,U), 0, 2048), partitionable threefry (modern default):
//   k1, k2 = split(rkey); key_i = tf(rkey,(0,i)) -> k2 = tf(rkey,(0,1))
//   lower_bits[f] = o0^o1 of tf(k2,(0,f));  span=2048 pow2 -> idx = bits & 2047
__global__ void rng_idx_kernel(uint32_t s0, uint32_t s1) {
    int f = blockIdx.x * blockDim.x + threadIdx.x;
    if (f < Lq * Uq) {
        uint32_t o0, o1;
        tf2x32(s0, s1, 0u, (uint32_t)f, o0, o1);
        g_idx[f] = (int)((o0 ^ o1) & 2047u);
    }
}

// ---------------- copy input x ------------------------------------------------
__global__ void copy_x_kernel(const float* __restrict__ src) {
    int t = blockIdx.x * blockDim.x + threadIdx.x;
    if (t < BLq * DMq) g_x[t] = src[t];
}

// ---------------- fp32 GEMM: C = A(MxK) * W(NxK)^T + bias ---------------------
#define GBM 64
#define GBN 64
#define GBK 16
__global__ void gemm_bias_kernel(const float* __restrict__ A,
                                 const float* __restrict__ W,
                                 const float* __restrict__ bias,
                                 float* __restrict__ C,
                                 int M, int N, int K) {
    __shared__ float As[GBK][GBM + 4];
    __shared__ float Ws[GBK][GBN + 4];
    int tid = threadIdx.x;                 // 256 threads
    int m0 = blockIdx.y * GBM;
    int n0 = blockIdx.x * GBN;
    int lr = tid >> 2;                     // 0..63
    int lc = (tid & 3) << 2;               // 0,4,8,12
    int ty = tid >> 4;                     // 0..15
    int tx = tid & 15;                     // 0..15
    float acc[4][4];
    #pragma unroll
    for (int i = 0; i < 4; i++)
        #pragma unroll
        for (int j = 0; j < 4; j++) acc[i][j] = 0.f;

    for (int k0 = 0; k0 < K; k0 += GBK) {
        float4 av = *(const float4*)&A[(size_t)(m0 + lr) * K + k0 + lc];
        float4 wv = *(const float4*)&W[(size_t)(n0 + lr) * K + k0 + lc];
        As[lc + 0][lr] = av.x; As[lc + 1][lr] = av.y;
        As[lc + 2][lr] = av.z; As[lc + 3][lr] = av.w;
        Ws[lc + 0][lr] = wv.x; Ws[lc + 1][lr] = wv.y;
        Ws[lc + 2][lr] = wv.z; Ws[lc + 3][lr] = wv.w;
        __syncthreads();
        #pragma unroll
        for (int kk = 0; kk < GBK; kk++) {
            float a[4], b[4];
            #pragma unroll
            for (int i = 0; i < 4; i++) a[i] = As[kk][ty * 4 + i];
            #pragma unroll
            for (int j = 0; j < 4; j++) b[j] = Ws[kk][tx * 4 + j];
            #pragma unroll
            for (int i = 0; i < 4; i++)
                #pragma unroll
                for (int j = 0; j < 4; j++) acc[i][j] += a[i] * b[j];
        }
        __syncthreads();
    }
    #pragma unroll
    for (int i = 0; i < 4; i++) {
        int m = m0 + ty * 4 + i;
        #pragma unroll
        for (int j = 0; j < 4; j++) {
            int n = n0 + tx * 4 + j;
            C[(size_t)m * N + n] = acc[i][j] + bias[n];
        }
    }
}

// ---------------- M = max_s(q.k_samp) - sum_s(q.k_samp)/Lk --------------------
__global__ void compute_M_kernel() {
    int t = blockIdx.x * blockDim.x + threadIdx.x;   // B*H*L
    if (t >= Bq * Hq * Lq) return;
    int l = t % Lq;
    int bh = t / Lq;
    int h = bh % Hq;
    int b = bh / Hq;
    const float* qrow = g_q + ((size_t)(b * Lq + l) * DMq + h * Eq);
    float qv[Eq];
    #pragma unroll
    for (int e = 0; e < Eq; e++) qv[e] = qrow[e];
    float mx = -INFINITY, sm = 0.f;
    for (int s = 0; s < Uq; s++) {
        int kl = g_idx[l * Uq + s];
        const float* krow = g_k + ((size_t)(b * Lq + kl) * DMq + h * Eq);
        float d = 0.f;
        #pragma unroll
        for (int e = 0; e < Eq; e++) d += qv[e] * krow[e];
        mx = fmaxf(mx, d);
        sm += d;
    }
    g_M[t] = mx - sm * (1.0f / (float)Lq);
}

// ---------------- top-k (top 40 of 2048, smaller-index tiebreak) --------------
__global__ void topk_kernel() {
    __shared__ float sv[Lq];
    __shared__ float rv[256];
    __shared__ int   ri[256];
    int bh = blockIdx.x;
    const float* Mrow = g_M + (size_t)bh * Lq;
    for (int i = threadIdx.x; i < Lq; i += 256) sv[i] = Mrow[i];
    __syncthreads();
    for (int it = 0; it < Uq; it++) {
        float best = -INFINITY; int bi = Lq;
        for (int i = threadIdx.x; i < Lq; i += 256) {
            float v = sv[i];
            if (v > best) { best = v; bi = i; }
        }
        rv[threadIdx.x] = best; ri[threadIdx.x] = bi;
        __syncthreads();
        for (int s = 128; s > 0; s >>= 1) {
            if (threadIdx.x < s) {
                float v2 = rv[threadIdx.x + s]; int i2 = ri[threadIdx.x + s];
                if (v2 > rv[threadIdx.x] ||
                    (v2 == rv[threadIdx.x] && i2 < ri[threadIdx.x])) {
                    rv[threadIdx.x] = v2; ri[threadIdx.x] = i2;
                }
            }
            __syncthreads();
        }
        if (threadIdx.x == 0) {
            g_top[bh * Uq + it] = ri[0];
            sv[ri[0]] = -INFINITY;
        }
        __syncthreads();
    }
}

// ---------------- mean of v over L per (b, channel) ---------------------------
__global__ void vmean_kernel() {
    int b = blockIdx.x;
    int d = threadIdx.x;
    float s = 0.f;
    for (int l = 0; l < Lq; l++) s += g_v[(size_t)(b * Lq + l) * DMq + d];
    g_vmean[b * DMq + d] = s * (1.0f / (float)Lq);
}

// ---------------- full attention for selected queries -------------------------
__global__ void attn_kernel() {
    __shared__ float sp[Lq];          // scores -> probs
    __shared__ float qs[Eq];
    __shared__ float red[256];
    __shared__ float wacc[8][Eq];
    const float SCALE = 0.17677669529663687f; // 1/sqrt(32)
    int blk = blockIdx.x;             // B*H*U
    int u = blk % Uq;
    int bh = blk / Uq;
    int h = bh % Hq;
    int b = bh / Hq;
    int lqi = g_top[bh * Uq + u];
    const float* qrow = g_q + ((size_t)(b * Lq + lqi) * DMq + h * Eq);
    if (threadIdx.x < Eq) qs[threadIdx.x] = qrow[threadIdx.x];
    __syncthreads();

    float lmax = -INFINITY;
    for (int kk = threadIdx.x; kk < Lq; kk += 256) {
        const float* krow = g_k + ((size_t)(b * Lq + kk) * DMq + h * Eq);
        float d = 0.f;
        #pragma unroll
        for (int e = 0; e < Eq; e++) d += qs[e] * krow[e];
        d *= SCALE;
        sp[kk] = d;
        lmax = fmaxf(lmax, d);
    }
    red[threadIdx.x] = lmax;
    __syncthreads();
    for (int s = 128; s > 0; s >>= 1) {
        if (threadIdx.x < s)
            red[threadIdx.x] = fmaxf(red[threadIdx.x], red[threadIdx.x + s]);
        __syncthreads();
    }
    float gmax = red[0];
    __syncthreads();

    float lsum = 0.f;
    for (int kk = threadIdx.x; kk < Lq; kk += 256) {
        float p = expf(sp[kk] - gmax);
        sp[kk] = p;
        lsum += p;
    }
    red[threadIdx.x] = lsum;
    __syncthreads();
    for (int s = 128; s > 0; s >>= 1) {
        if (threadIdx.x < s) red[threadIdx.x] += red[threadIdx.x + s];
        __syncthreads();
    }
    float inv = 1.0f / red[0];
    __syncthreads();

    float acc[Eq];
    #pragma unroll
    for (int e = 0; e < Eq; e++) acc[e] = 0.f;
    for (int kk = threadIdx.x; kk < Lq; kk += 256) {
        float p = sp[kk];
        const float* vrow = g_v + ((size_t)(b * Lq + kk) * DMq + h * Eq);
        #pragma unroll
        for (int e = 0; e < Eq; e++) acc[e] += p * vrow[e];
    }
    int lane = threadIdx.x & 31;
    int wid = threadIdx.x >> 5;
    #pragma unroll
    for (int e = 0; e < Eq; e++) {
        float v = acc[e];
        #pragma unroll
        for (int off = 16; off > 0; off >>= 1)
            v += __shfl_down_sync(0xffffffffu, v, off);
        if (lane == 0) wacc[wid][e] = v;
    }
    __syncthreads();
    if (threadIdx.x < Eq) {
        int e = threadIdx.x;
        float s = 0.f;
        #pragma unroll
        for (int w = 0; w < 8; w++) s += wacc[w][e];
        g_upd[((size_t)bh * Uq + u) * Eq + e] = s * inv;
    }
}

// ---------------- ctx assembly ------------------------------------------------
__global__ void ctx_fill_kernel() {
    int t = blockIdx.x * blockDim.x + threadIdx.x;
    if (t >= BLq * DMq) return;
    int d = t % DMq;
    int bl = t / DMq;
    int b = bl / Lq;
    g_ctx[t] = g_vmean[b * DMq + d];
}

__global__ void ctx_scatter_kernel() {
    int t = blockIdx.x * blockDim.x + threadIdx.x;  // B*H*U*E
    if (t >= Bq * Hq * Uq * Eq) return;
    int e = t % Eq;
    int rest = t / Eq;
    int u = rest % Uq;
    int bh = rest / Uq;
    int h = bh % Hq;
    int b = bh / Hq;
    int l = g_top[bh * Uq + u];
    g_ctx[(size_t)(b * Lq + l) * DMq + h * Eq + e] = g_upd[t];
}

// ---------------- residual add (g_tmp) + LayerNorm (in-place on g_x) ----------
__global__ void add_ln_kernel(const float* __restrict__ gam,
                              const float* __restrict__ bet) {
    __shared__ float red[256];
    int row = blockIdx.x;
    int d = threadIdx.x;
    size_t off = (size_t)row * DMq + d;
    float v = g_x[off] + g_tmp[off];
    red[d] = v;
    __syncthreads();
    for (int s = 128; s > 0; s >>= 1) {
        if (d < s) red[d] += red[d + s];
        __syncthreads();
    }
    float m = red[0] * (1.0f / (float)DMq);
    __syncthreads();
    float c = v - m;
    red[d] = c * c;
    __syncthreads();
    for (int s = 128; s > 0; s >>= 1) {
        if (d < s) red[d] += red[d + s];
        __syncthreads();
    }
    float var = red[0] * (1.0f / (float)DMq);
    g_x[off] = c * rsqrtf(var + 1e-5f) * gam[d] + bet[d];
}

// ---------------- fused FFN + residual + LN (in-place on g_x) -----------------
__global__ void ffn_ln_kernel(const float* __restrict__ c1w,
                              const float* __restrict__ c1b,
                              const float* __restrict__ c2w,
                              const float* __restrict__ c2b,
                              const float* __restrict__ gam,
                              const float* __restrict__ bet) {
    __shared__ float xs[DMq];
    __shared__ float ys[INTERq];
    __shared__ float red[256];
    int row = blockIdx.x;
    int d = threadIdx.x;
    size_t off = (size_t)row * DMq + d;
    float xv = g_x[off];
    xs[d] = xv;
    __syncthreads();
    if (d < INTERq) {
        float a = c1b[d];
        const float* wrow = c1w + (size_t)d * DMq;
        for (int k = 0; k < DMq; k++) a += xs[k] * wrow[k];
        ys[d] = fmaxf(a, 0.f);
    }
    __syncthreads();
    float a2 = c2b[d];
    const float* w2 = c2w + (size_t)d * INTERq;
    #pragma unroll
    for (int f = 0; f < INTERq; f++) a2 += ys[f] * w2[f];
    float v = xv + a2;
    red[d] = v;
    __syncthreads();
    for (int s = 128; s > 0; s >>= 1) {
        if (d < s) red[d] += red[d + s];
        __syncthreads();
    }
    float m = red[0] * (1.0f / (float)DMq);
    __syncthreads();
    float c = v - m;
    red[d] = c * c;
    __syncthreads();
    for (int s = 128; s > 0; s >>= 1) {
        if (d < s) red[d] += red[d + s];
        __syncthreads();
    }
    float var = red[0] * (1.0f / (float)DMq);
    g_x[off] = c * rsqrtf(var + 1e-5f) * gam[d] + bet[d];
}

// ---------------- distill conv (circular pad, k=3) -> g_tmp (b,l,o) -----------
__global__ void conv_kernel(const float* __restrict__ W,
                            const float* __restrict__ cb) {
    __shared__ float xs[18][DMq];
    int b = blockIdx.y;
    int l0 = blockIdx.x * 16;
    int o = threadIdx.x;
    for (int r = 0; r < 18; r++) {
        int l = l0 - 1 + r;
        l = (l + Lq) % Lq;
        xs[r][o] = g_x[(size_t)(b * Lq + l) * DMq + o];
    }
    __syncthreads();
    float acc[16];
    float bias = cb[o];
    #pragma unroll
    for (int j = 0; j < 16; j++) acc[j] = bias;
    const float* wrow = W + (size_t)o * DMq * 3;
    for (int i = 0; i < DMq; i++) {
        float w0 = wrow[i * 3 + 0];
        float w1 = wrow[i * 3 + 1];
        float w2 = wrow[i * 3 + 2];
        #pragma unroll
        for (int j = 0; j < 16; j++)
            acc[j] += xs[j][i] * w0 + xs[j + 1][i] * w1 + xs[j + 2][i] * w2;
    }
    #pragma unroll
    for (int j = 0; j < 16; j++)
        g_tmp[(size_t)(b * Lq + l0 + j) * DMq + o] = acc[j];
}

// ---------------- batchnorm stats (deterministic, fixed order) ----------------
__global__ void bn_part_kernel() {
    int chunk = blockIdx.x;   // 32 chunks of 256 rows
    int d = threadIdx.x;
    float s = 0.f, s2 = 0.f;
    int r0 = chunk * 256;
    for (int r = 0; r < 256; r++) {
        float v = g_tmp[(size_t)(r0 + r) * DMq + d];
        s += v; s2 += v * v;
    }
    g_bnp1[chunk * DMq + d] = s;
    g_bnp2[chunk * DMq + d] = s2;
}

__global__ void bn_final_kernel() {
    int d = threadIdx.x;
    float s = 0.f, s2 = 0.f;
    for (int c = 0; c < 32; c++) {
        s  += g_bnp1[c * DMq + d];
        s2 += g_bnp2[c * DMq + d];
    }
    float m = s * (1.0f / (float)BLq);
    g_bnm[d] = m;
    g_bnv[d] = s2 * (1.0f / (float)BLq) - m * m;
}

__global__ void bn_elu_kernel(const float* __restrict__ gam,
                              const float* __restrict__ bet) {
    int t = blockIdx.x * blockDim.x + threadIdx.x;
    if (t >= BLq * DMq) return;
    int d = t % DMq;
    float y = (g_tmp[t] - g_bnm[d]) * rsqrtf(g_bnv[d] + 1e-5f) * gam[d] + bet[d];
    g_x[t] = (y > 0.f) ? y : expm1f(y);
}

// ---------------- final LayerNorm into d_out ----------------------------------
__global__ void final_ln_kernel(const float* __restrict__ gam,
                                const float* __restrict__ bet,
                                float* __restrict__ out) {
    __shared__ float red[256];
    int row = blockIdx.x;
    int d = threadIdx.x;
    size_t off = (size_t)row * DMq + d;
    float v = g_x[off];
    red[d] = v;
    __syncthreads();
    for (int s = 128; s > 0; s >>= 1) {
        if (d < s) red[d] += red[d + s];
        __syncthreads();
    }
    float m = red[0] * (1.0f / (float)DMq);
    __syncthreads();
    float c = v - m;
    red[d] = c * c;
    __syncthreads();
    for (int s = 128; s > 0; s >>= 1) {
        if (d < s) red[d] += red[d + s];
        __syncthreads();
    }
    float var = red[0] * (1.0f / (float)DMq);
    out[off] = c * rsqrtf(var + 1e-5f) * gam[d] + bet[d];
}

// ---------------- host driver -------------------------------------------------
extern "C" void kernel_launch(void* const* d_in, const int* in_sizes, int n_in,
                              void* d_out, int out_size) {
    const float* x_in = (const float*)d_in[0];
    const float* wq   = (const float*)d_in[1];
    const float* bq   = (const float*)d_in[2];
    const float* wk   = (const float*)d_in[3];
    const float* bk   = (const float*)d_in[4];
    const float* wv   = (const float*)d_in[5];
    const float* bv   = (const float*)d_in[6];
    const float* wo   = (const float*)d_in[7];
    const float* bo   = (const float*)d_in[8];
    const float* c1w  = (const float*)d_in[9];
    const float* c1b  = (const float*)d_in[10];
    const float* c2w  = (const float*)d_in[11];
    const float* c2b  = (const float*)d_in[12];
    const float* ln1g = (const float*)d_in[13];
    const float* ln1b = (const float*)d_in[14];
    const float* ln2g = (const float*)d_in[15];
    const float* ln2b = (const float*)d_in[16];
    const float* dcw  = (const float*)d_in[17];
    const float* dcb  = (const float*)d_in[18];
    const float* bng  = (const float*)d_in[19];
    const float* bnb  = (const float*)d_in[20];
    const float* fng  = (const float*)d_in[21];
    const float* fnb  = (const float*)d_in[22];
    float* out = (float*)d_out;

    // *** REAL device addresses of __device__ globals (host shadow is a trap
    // on GB300: ATS makes the wrong pointer silently "work" against host BSS).
    void *vp;
    cudaGetSymbolAddress(&vp, g_x);   float* px   = (float*)vp;
    cudaGetSymbolAddress(&vp, g_q);   float* pq   = (float*)vp;
    cudaGetSymbolAddress(&vp, g_k);   float* pk   = (float*)vp;
    cudaGetSymbolAddress(&vp, g_v);   float* pv   = (float*)vp;
    cudaGetSymbolAddress(&vp, g_ctx); float* pctx = (float*)vp;
    cudaGetSymbolAddress(&vp, g_tmp); float* ptmp = (float*)vp;

    copy_x_kernel<<<(BLq * DMq) / 256, 256>>>(x_in);

    dim3 ggrid(DMq / GBN, BLq / GBM);   // (4, 128)

    for (int lay = 0; lay < NLq; lay++) {
        const float* WQ = wq + (size_t)lay * DMq * DMq;
        const float* WK = wk + (size_t)lay * DMq * DMq;
        const float* WV = wv + (size_t)lay * DMq * DMq;
        const float* WO = wo + (size_t)lay * DMq * DMq;
        const float* BQp = bq + (size_t)lay * DMq;
        const float* BKp = bk + (size_t)lay * DMq;
        const float* BVp = bv + (size_t)lay * DMq;
        const float* BOp = bo + (size_t)lay * DMq;

        gemm_bias_kernel<<<ggrid, 256>>>(px, WQ, BQp, pq, BLq, DMq, DMq);
        gemm_bias_kernel<<<ggrid, 256>>>(px, WK, BKp, pk, BLq, DMq, DMq);
        gemm_bias_kernel<<<ggrid, 256>>>(px, WV, BVp, pv, BLq, DMq, DMq);

        // layer key = fold_in(key(42), lay) = tf((0,42), (0,lay))
        uint32_t k0, k1;
        tf2x32(0u, 42u, 0u, (uint32_t)lay, k0, k1);
        // randint lower_bits come from split(rkey)[1]; partitionable split:
        // k2 = tf(layer_key, (0, 1))
        uint32_t s0, s1;
        tf2x32(k0, k1, 0u, 1u, s0, s1);
        rng_idx_kernel<<<(Lq * Uq + 255) / 256, 256>>>(s0, s1);

        compute_M_kernel<<<(Bq * Hq * Lq) / 256, 256>>>();
        topk_kernel<<<Bq * Hq, 256>>>();
        vmean_kernel<<<Bq, DMq>>>();
        attn_kernel<<<Bq * Hq * Uq, 256>>>();
        ctx_fill_kernel<<<(BLq * DMq) / 256, 256>>>();
        ctx_scatter_kernel<<<(Bq * Hq * Uq * Eq + 255) / 256, 256>>>();

        gemm_bias_kernel<<<ggrid, 256>>>(pctx, WO, BOp, ptmp, BLq, DMq, DMq);
        add_ln_kernel<<<BLq, DMq>>>(ln1g + (size_t)lay * DMq,
                                    ln1b + (size_t)lay * DMq);
        ffn_ln_kernel<<<BLq, DMq>>>(c1w + (size_t)lay * INTERq * DMq,
                                    c1b + (size_t)lay * INTERq,
                                    c2w + (size_t)lay * DMq * INTERq,
                                    c2b + (size_t)lay * DMq,
                                    ln2g + (size_t)lay * DMq,
                                    ln2b + (size_t)lay * DMq);

        if (lay < NLq - 1) {
            conv_kernel<<<dim3(Lq / 16, Bq), DMq>>>(
                dcw + (size_t)lay * DMq * DMq * 3,
                dcb + (size_t)lay * DMq);
            bn_part_kernel<<<32, DMq>>>();
            bn_final_kernel<<<1, DMq>>>();
            bn_elu_kernel<<<(BLq * DMq) / 256, 256>>>(
                bng + (size_t)lay * DMq,
                bnb + (size_t)lay * DMq);
        }
    }

    final_ln_kernel<<<BLq, DMq>>>(fng, fnb, out);
}

// round 5
// speedup vs baseline: 2.2141x; 2.2141x over previous
#include <cuda_runtime.h>
#include <cuda_bf16.h>
#include <math.h>
#include <stdint.h>

// Problem constants
#define Bq   4
#define Lq   2048
#define DMq  256
#define Hq   8
#define Eq   32
#define NLq  3
#define INTERq 16
#define Uq   40
#define BLq  (Bq*Lq)     // 8192

// ---------------- scratch (device globals; no allocation allowed) -------------
__device__ float g_x[BLq*DMq];
__device__ float g_q[BLq*DMq];
__device__ float g_k[BLq*DMq];
__device__ float g_v[BLq*DMq];
__device__ float g_ctx[BLq*DMq];
__device__ float g_tmp[BLq*DMq];
__device__ float g_wt[3*DMq*DMq];       // transposed conv weights [t][o][i]
__device__ int   g_idx[Lq*Uq];
__device__ float g_M[Bq*Hq*Lq];
__device__ int   g_top[Bq*Hq*Uq];
__device__ float g_vmean[Bq*DMq];
__device__ float g_vpart[Bq*32*DMq];
__device__ float g_upd[Bq*Hq*Uq*Eq];
__device__ float g_bnp1[32*DMq];
__device__ float g_bnp2[32*DMq];
__device__ float g_bnm[DMq];
__device__ float g_bnv[DMq];

// ---------------- Threefry-2x32 (matches JAX) ---------------------------------
__host__ __device__ inline void tf2x32(uint32_t k0, uint32_t k1,
                                       uint32_t x0, uint32_t x1,
                                       uint32_t& o0, uint32_t& o1) {
    uint32_t ks[3];
    ks[0] = k0; ks[1] = k1; ks[2] = k0 ^ k1 ^ 0x1BD11BDAu;
    x0 += ks[0]; x1 += ks[1];
    const int R0[4] = {13, 15, 26, 6};
    const int R1[4] = {17, 29, 16, 24};
    #pragma unroll
    for (int i = 0; i < 5; i++) {
        #pragma unroll
        for (int j = 0; j < 4; j++) {
            int r = (i & 1) ? R1[j] : R0[j];
            x0 += x1;
            x1 = (x1 << r) | (x1 >> (32 - r));
            x1 ^= x0;
        }
        x0 += ks[(i + 1) % 3];
        x1 += ks[(i + 2) % 3] + (uint32_t)(i + 1);
    }
    o0 = x0; o1 = x1;
}

__global__ void rng_idx_kernel(uint32_t s0, uint32_t s1) {
    int f = blockIdx.x * blockDim.x + threadIdx.x;
    if (f < Lq * Uq) {
        uint32_t o0, o1;
        tf2x32(s0, s1, 0u, (uint32_t)f, o0, o1);
        g_idx[f] = (int)((o0 ^ o1) & 2047u);
    }
}

// ---------------- copy input x (vectorized) -----------------------------------
__global__ void copy_x_kernel(const float4* __restrict__ src) {
    int t = blockIdx.x * blockDim.x + threadIdx.x;
    if (t < BLq * DMq / 4) ((float4*)g_x)[t] = src[t];
}

// ---------------- fp32 GEMM 128x64 tile: C = A(Mx256) * W(256x256)^T + bias ---
// grid (4, 64), 256 threads, 8x4 per thread
__global__ void gemm128_kernel(const float* __restrict__ A,
                               const float* __restrict__ W,
                               const float* __restrict__ bias,
                               float* __restrict__ C) {
    __shared__ float As[16][132];
    __shared__ float Ws[16][68];
    const int K = DMq;
    int tid = threadIdx.x;
    int m0 = blockIdx.y * 128;
    int n0 = blockIdx.x * 64;
    int alr = tid >> 1;                // 0..127
    int alc = (tid & 1) * 8;           // 0 or 8
    int wlr = tid >> 2;                // 0..63
    int wlc = (tid & 3) * 4;           // 0,4,8,12
    int ty = tid >> 4;                 // 0..15 -> 8 rows
    int tx = tid & 15;                 // 0..15 -> 4 cols
    float acc[8][4];
    #pragma unroll
    for (int i = 0; i < 8; i++)
        #pragma unroll
        for (int j = 0; j < 4; j++) acc[i][j] = 0.f;

    for (int k0 = 0; k0 < K; k0 += 16) {
        float4 a0 = *(const float4*)&A[(size_t)(m0 + alr) * K + k0 + alc];
        float4 a1 = *(const float4*)&A[(size_t)(m0 + alr) * K + k0 + alc + 4];
        float4 wv = *(const float4*)&W[(size_t)(n0 + wlr) * K + k0 + wlc];
        As[alc + 0][alr] = a0.x; As[alc + 1][alr] = a0.y;
        As[alc + 2][alr] = a0.z; As[alc + 3][alr] = a0.w;
        As[alc + 4][alr] = a1.x; As[alc + 5][alr] = a1.y;
        As[alc + 6][alr] = a1.z; As[alc + 7][alr] = a1.w;
        Ws[wlc + 0][wlr] = wv.x; Ws[wlc + 1][wlr] = wv.y;
        Ws[wlc + 2][wlr] = wv.z; Ws[wlc + 3][wlr] = wv.w;
        __syncthreads();
        #pragma unroll
        for (int kk = 0; kk < 16; kk++) {
            float a[8], b[4];
            #pragma unroll
            for (int i = 0; i < 8; i++) a[i] = As[kk][ty * 8 + i];
            #pragma unroll
            for (int j = 0; j < 4; j++) b[j] = Ws[kk][tx * 4 + j];
            #pragma unroll
            for (int i = 0; i < 8; i++)
                #pragma unroll
                for (int j = 0; j < 4; j++) acc[i][j] += a[i] * b[j];
        }
        __syncthreads();
    }
    #pragma unroll
    for (int i = 0; i < 8; i++) {
        int m = m0 + ty * 8 + i;
        #pragma unroll
        for (int j = 0; j < 4; j++) {
            int n = n0 + tx * 4 + j;
            C[(size_t)m * DMq + n] = acc[i][j] + bias[n];
        }
    }
}

// ---------------- conv weight transpose: dcw[o][i][t] -> g_wt[t][o][i] --------
__global__ void wtrans_kernel(const float* __restrict__ dcw) {
    int o = blockIdx.x;
    int i = threadIdx.x;
    #pragma unroll
    for (int t = 0; t < 3; t++)
        g_wt[t * DMq * DMq + o * DMq + i] = dcw[(size_t)o * DMq * 3 + i * 3 + t];
}

// ---------------- conv as 3-tap GEMM (circular rows), 128x64 tile -------------
__global__ void convgemm_kernel(const float* __restrict__ cb) {
    __shared__ float As[16][132];
    __shared__ float Ws[16][68];
    int tid = threadIdx.x;
    int m0 = blockIdx.y * 128;
    int n0 = blockIdx.x * 64;
    int alr = tid >> 1;
    int alc = (tid & 1) * 8;
    int wlr = tid >> 2;
    int wlc = (tid & 3) * 4;
    int ty = tid >> 4;
    int tx = tid & 15;
    float acc[8][4];
    #pragma unroll
    for (int i = 0; i < 8; i++)
        #pragma unroll
        for (int j = 0; j < 4; j++) acc[i][j] = 0.f;

    int m = m0 + alr;
    int b = m >> 11;
    int l = m & 2047;

    for (int t = 0; t < 3; t++) {
        int rowA = (b << 11) | ((l + t + 2047) & 2047);   // l + t - 1 mod L
        const float* Arow = g_x + (size_t)rowA * DMq;
        const float* Wt = g_wt + (size_t)t * DMq * DMq;
        for (int k0 = 0; k0 < DMq; k0 += 16) {
            float4 a0 = *(const float4*)&Arow[k0 + alc];
            float4 a1 = *(const float4*)&Arow[k0 + alc + 4];
            float4 wv = *(const float4*)&Wt[(size_t)(n0 + wlr) * DMq + k0 + wlc];
            As[alc + 0][alr] = a0.x; As[alc + 1][alr] = a0.y;
            As[alc + 2][alr] = a0.z; As[alc + 3][alr] = a0.w;
            As[alc + 4][alr] = a1.x; As[alc + 5][alr] = a1.y;
            As[alc + 6][alr] = a1.z; As[alc + 7][alr] = a1.w;
            Ws[wlc + 0][wlr] = wv.x; Ws[wlc + 1][wlr] = wv.y;
            Ws[wlc + 2][wlr] = wv.z; Ws[wlc + 3][wlr] = wv.w;
            __syncthreads();
            #pragma unroll
            for (int kk = 0; kk < 16; kk++) {
                float a[8], bb[4];
                #pragma unroll
                for (int i = 0; i < 8; i++) a[i] = As[kk][ty * 8 + i];
                #pragma unroll
                for (int j = 0; j < 4; j++) bb[j] = Ws[kk][tx * 4 + j];
                #pragma unroll
                for (int i = 0; i < 8; i++)
                    #pragma unroll
                    for (int j = 0; j < 4; j++) acc[i][j] += a[i] * bb[j];
            }
            __syncthreads();
        }
    }
    #pragma unroll
    for (int i = 0; i < 8; i++) {
        int mm = m0 + ty * 8 + i;
        #pragma unroll
        for (int j = 0; j < 4; j++) {
            int n = n0 + tx * 4 + j;
            g_tmp[(size_t)mm * DMq + n] = acc[i][j] + cb[n];
        }
    }
}

// ---------------- M = max_s(q.k_samp) - sum_s(q.k_samp)/Lk (float4) -----------
__global__ void compute_M_kernel() {
    int t = blockIdx.x * blockDim.x + threadIdx.x;
    if (t >= Bq * Hq * Lq) return;
    int l = t % Lq;
    int bh = t / Lq;
    int h = bh % Hq;
    int b = bh / Hq;
    const float4* q4 = (const float4*)(g_q + ((size_t)(b * Lq + l) * DMq + h * Eq));
    float4 qv[8];
    #pragma unroll
    for (int j = 0; j < 8; j++) qv[j] = q4[j];
    float mx = -INFINITY, sm = 0.f;
    for (int s = 0; s < Uq; s++) {
        int kl = g_idx[l * Uq + s];
        const float4* k4 = (const float4*)(g_k + ((size_t)(b * Lq + kl) * DMq + h * Eq));
        float d = 0.f;
        #pragma unroll
        for (int j = 0; j < 8; j++) {
            float4 kv = k4[j];
            d += qv[j].x * kv.x + qv[j].y * kv.y + qv[j].z * kv.z + qv[j].w * kv.w;
        }
        mx = fmaxf(mx, d);
        sm += d;
    }
    g_M[t] = mx - sm * (1.0f / (float)Lq);
}

// ---------------- top-k (top 40 of 2048, smaller-index tiebreak) --------------
__global__ void topk_kernel() {
    __shared__ float sv[Lq];
    __shared__ float rv[256];
    __shared__ int   ri[256];
    int bh = blockIdx.x;
    const float* Mrow = g_M + (size_t)bh * Lq;
    for (int i = threadIdx.x; i < Lq; i += 256) sv[i] = Mrow[i];
    __syncthreads();
    for (int it = 0; it < Uq; it++) {
        float best = -INFINITY; int bi = Lq;
        for (int i = threadIdx.x; i < Lq; i += 256) {
            float v = sv[i];
            if (v > best) { best = v; bi = i; }
        }
        rv[threadIdx.x] = best; ri[threadIdx.x] = bi;
        __syncthreads();
        for (int s = 128; s > 0; s >>= 1) {
            if (threadIdx.x < s) {
                float v2 = rv[threadIdx.x + s]; int i2 = ri[threadIdx.x + s];
                if (v2 > rv[threadIdx.x] ||
                    (v2 == rv[threadIdx.x] && i2 < ri[threadIdx.x])) {
                    rv[threadIdx.x] = v2; ri[threadIdx.x] = i2;
                }
            }
            __syncthreads();
        }
        if (threadIdx.x == 0) {
            g_top[bh * Uq + it] = ri[0];
            sv[ri[0]] = -INFINITY;
        }
        __syncthreads();
    }
}

// ---------------- mean of v over L: two-stage ---------------------------------
__global__ void vmean_part_kernel() {
    int b = blockIdx.y;
    int chunk = blockIdx.x;            // 0..31, 64 rows each
    int d = threadIdx.x;
    float s = 0.f;
    int r0 = chunk * 64;
    for (int r = 0; r < 64; r++)
        s += g_v[(size_t)(b * Lq + r0 + r) * DMq + d];
    g_vpart[(size_t)(b * 32 + chunk) * DMq + d] = s;
}

__global__ void vmean_final_kernel() {
    int b = blockIdx.x;
    int d = threadIdx.x;
    float s = 0.f;
    for (int c = 0; c < 32; c++) s += g_vpart[(size_t)(b * 32 + c) * DMq + d];
    g_vmean[b * DMq + d] = s * (1.0f / (float)Lq);
}

// ---------------- full attention for selected queries (float4) ----------------
__global__ void attn_kernel() {
    __shared__ float sp[Lq];
    __shared__ float qs[Eq];
    __shared__ float red[256];
    __shared__ float wacc[8][Eq];
    const float SCALE = 0.17677669529663687f;
    int blk = blockIdx.x;
    int u = blk % Uq;
    int bh = blk / Uq;
    int h = bh % Hq;
    int b = bh / Hq;
    int lqi = g_top[bh * Uq + u];
    const float* qrow = g_q + ((size_t)(b * Lq + lqi) * DMq + h * Eq);
    if (threadIdx.x < Eq) qs[threadIdx.x] = qrow[threadIdx.x];
    __syncthreads();

    float lmax = -INFINITY;
    for (int kk = threadIdx.x; kk < Lq; kk += 256) {
        const float4* k4 = (const float4*)(g_k + ((size_t)(b * Lq + kk) * DMq + h * Eq));
        float d = 0.f;
        #pragma unroll
        for (int j = 0; j < 8; j++) {
            float4 kv = k4[j];
            d += qs[4*j+0] * kv.x + qs[4*j+1] * kv.y + qs[4*j+2] * kv.z + qs[4*j+3] * kv.w;
        }
        d *= SCALE;
        sp[kk] = d;
        lmax = fmaxf(lmax, d);
    }
    red[threadIdx.x] = lmax;
    __syncthreads();
    for (int s = 128; s > 0; s >>= 1) {
        if (threadIdx.x < s)
            red[threadIdx.x] = fmaxf(red[threadIdx.x], red[threadIdx.x + s]);
        __syncthreads();
    }
    float gmax = red[0];
    __syncthreads();

    float lsum = 0.f;
    for (int kk = threadIdx.x; kk < Lq; kk += 256) {
        float p = expf(sp[kk] - gmax);
        sp[kk] = p;
        lsum += p;
    }
    red[threadIdx.x] = lsum;
    __syncthreads();
    for (int s = 128; s > 0; s >>= 1) {
        if (threadIdx.x < s) red[threadIdx.x] += red[threadIdx.x + s];
        __syncthreads();
    }
    float inv = 1.0f / red[0];
    __syncthreads();

    float acc[Eq];
    #pragma unroll
    for (int e = 0; e < Eq; e++) acc[e] = 0.f;
    for (int kk = threadIdx.x; kk < Lq; kk += 256) {
        float p = sp[kk];
        const float4* v4 = (const float4*)(g_v + ((size_t)(b * Lq + kk) * DMq + h * Eq));
        #pragma unroll
        for (int j = 0; j < 8; j++) {
            float4 vv = v4[j];
            acc[4*j+0] += p * vv.x; acc[4*j+1] += p * vv.y;
            acc[4*j+2] += p * vv.z; acc[4*j+3] += p * vv.w;
        }
    }
    int lane = threadIdx.x & 31;
    int wid = threadIdx.x >> 5;
    #pragma unroll
    for (int e = 0; e < Eq; e++) {
        float v = acc[e];
        #pragma unroll
        for (int off = 16; off > 0; off >>= 1)
            v += __shfl_down_sync(0xffffffffu, v, off);
        if (lane == 0) wacc[wid][e] = v;
    }
    __syncthreads();
    if (threadIdx.x < Eq) {
        int e = threadIdx.x;
        float s = 0.f;
        #pragma unroll
        for (int w = 0; w < 8; w++) s += wacc[w][e];
        g_upd[((size_t)bh * Uq + u) * Eq + e] = s * inv;
    }
}

// ---------------- ctx assembly ------------------------------------------------
__global__ void ctx_fill_kernel() {
    int t = blockIdx.x * blockDim.x + threadIdx.x;
    if (t >= BLq * DMq) return;
    int d = t % DMq;
    int bl = t / DMq;
    int b = bl / Lq;
    g_ctx[t] = g_vmean[b * DMq + d];
}

__global__ void ctx_scatter_kernel() {
    int t = blockIdx.x * blockDim.x + threadIdx.x;
    if (t >= Bq * Hq * Uq * Eq) return;
    int e = t % Eq;
    int rest = t / Eq;
    int u = rest % Uq;
    int bh = rest / Uq;
    int h = bh % Hq;
    int b = bh / Hq;
    int l = g_top[bh * Uq + u];
    g_ctx[(size_t)(b * Lq + l) * DMq + h * Eq + e] = g_upd[t];
}

// ---------------- fused: LN1(x+tmp) -> FFN -> +res -> LN2, in-place on g_x ----
__global__ void post_kernel(const float* __restrict__ c1w,
                            const float* __restrict__ c1b,
                            const float* __restrict__ c2w,
                            const float* __restrict__ c2b,
                            const float* __restrict__ g1,
                            const float* __restrict__ b1,
                            const float* __restrict__ g2,
                            const float* __restrict__ b2) {
    __shared__ float xs[DMq];
    __shared__ float ys[INTERq];
    __shared__ float red[256];
    int row = blockIdx.x;
    int d = threadIdx.x;
    size_t off = (size_t)row * DMq + d;
    float v = g_x[off] + g_tmp[off];
    red[d] = v;
    __syncthreads();
    for (int s = 128; s > 0; s >>= 1) {
        if (d < s) red[d] += red[d + s];
        __syncthreads();
    }
    float m = red[0] * (1.0f / (float)DMq);
    __syncthreads();
    float c = v - m;
    red[d] = c * c;
    __syncthreads();
    for (int s = 128; s > 0; s >>= 1) {
        if (d < s) red[d] += red[d + s];
        __syncthreads();
    }
    float var = red[0] * (1.0f / (float)DMq);
    float x1 = c * rsqrtf(var + 1e-5f) * g1[d] + b1[d];
    __syncthreads();
    xs[d] = x1;
    __syncthreads();
    if (d < INTERq) {
        float a = c1b[d];
        const float* wrow = c1w + (size_t)d * DMq;
        for (int k = 0; k < DMq; k++) a += xs[k] * wrow[k];
        ys[d] = fmaxf(a, 0.f);
    }
    __syncthreads();
    float a2 = c2b[d];
    const float* w2 = c2w + (size_t)d * INTERq;
    #pragma unroll
    for (int f = 0; f < INTERq; f++) a2 += ys[f] * w2[f];
    float v2 = x1 + a2;
    red[d] = v2;
    __syncthreads();
    for (int s = 128; s > 0; s >>= 1) {
        if (d < s) red[d] += red[d + s];
        __syncthreads();
    }
    float m2 = red[0] * (1.0f / (float)DMq);
    __syncthreads();
    float c2 = v2 - m2;
    red[d] = c2 * c2;
    __syncthreads();
    for (int s = 128; s > 0; s >>= 1) {
        if (d < s) red[d] += red[d + s];
        __syncthreads();
    }
    float var2 = red[0] * (1.0f / (float)DMq);
    g_x[off] = c2 * rsqrtf(var2 + 1e-5f) * g2[d] + b2[d];
}

// ---------------- batchnorm stats (deterministic, fixed order) ----------------
__global__ void bn_part_kernel() {
    int chunk = blockIdx.x;
    int d = threadIdx.x;
    float s = 0.f, s2 = 0.f;
    int r0 = chunk * 256;
    for (int r = 0; r < 256; r++) {
        float v = g_tmp[(size_t)(r0 + r) * DMq + d];
        s += v; s2 += v * v;
    }
    g_bnp1[chunk * DMq + d] = s;
    g_bnp2[chunk * DMq + d] = s2;
}

__global__ void bn_final_kernel() {
    int d = threadIdx.x;
    float s = 0.f, s2 = 0.f;
    for (int c = 0; c < 32; c++) {
        s  += g_bnp1[c * DMq + d];
        s2 += g_bnp2[c * DMq + d];
    }
    float m = s * (1.0f / (float)BLq);
    g_bnm[d] = m;
    g_bnv[d] = s2 * (1.0f / (float)BLq) - m * m;
}

__global__ void bn_elu_kernel(const float* __restrict__ gam,
                              const float* __restrict__ bet) {
    int t = blockIdx.x * blockDim.x + threadIdx.x;
    if (t >= BLq * DMq) return;
    int d = t % DMq;
    float y = (g_tmp[t] - g_bnm[d]) * rsqrtf(g_bnv[d] + 1e-5f) * gam[d] + bet[d];
    g_x[t] = (y > 0.f) ? y : expm1f(y);
}

// ---------------- final LayerNorm into d_out ----------------------------------
__global__ void final_ln_kernel(const float* __restrict__ gam,
                                const float* __restrict__ bet,
                                float* __restrict__ out) {
    __shared__ float red[256];
    int row = blockIdx.x;
    int d = threadIdx.x;
    size_t off = (size_t)row * DMq + d;
    float v = g_x[off];
    red[d] = v;
    __syncthreads();
    for (int s = 128; s > 0; s >>= 1) {
        if (d < s) red[d] += red[d + s];
        __syncthreads();
    }
    float m = red[0] * (1.0f / (float)DMq);
    __syncthreads();
    float c = v - m;
    red[d] = c * c;
    __syncthreads();
    for (int s = 128; s > 0; s >>= 1) {
        if (d < s) red[d] += red[d + s];
        __syncthreads();
    }
    float var = red[0] * (1.0f / (float)DMq);
    out[off] = c * rsqrtf(var + 1e-5f) * gam[d] + bet[d];
}

// ---------------- host driver -------------------------------------------------
extern "C" void kernel_launch(void* const* d_in, const int* in_sizes, int n_in,
                              void* d_out, int out_size) {
    const float* x_in = (const float*)d_in[0];
    const float* wq   = (const float*)d_in[1];
    const float* bq   = (const float*)d_in[2];
    const float* wk   = (const float*)d_in[3];
    const float* bk   = (const float*)d_in[4];
    const float* wv   = (const float*)d_in[5];
    const float* bv   = (const float*)d_in[6];
    const float* wo   = (const float*)d_in[7];
    const float* bo   = (const float*)d_in[8];
    const float* c1w  = (const float*)d_in[9];
    const float* c1b  = (const float*)d_in[10];
    const float* c2w  = (const float*)d_in[11];
    const float* c2b  = (const float*)d_in[12];
    const float* ln1g = (const float*)d_in[13];
    const float* ln1b = (const float*)d_in[14];
    const float* ln2g = (const float*)d_in[15];
    const float* ln2b = (const float*)d_in[16];
    const float* dcw  = (const float*)d_in[17];
    const float* dcb  = (const float*)d_in[18];
    const float* bng  = (const float*)d_in[19];
    const float* bnb  = (const float*)d_in[20];
    const float* fng  = (const float*)d_in[21];
    const float* fnb  = (const float*)d_in[22];
    float* out = (float*)d_out;

    // Real device addresses of __device__ globals (host-shadow/ATS trap on GB300)
    void *vp;
    cudaGetSymbolAddress(&vp, g_x);   float* px   = (float*)vp;
    cudaGetSymbolAddress(&vp, g_q);   float* pq   = (float*)vp;
    cudaGetSymbolAddress(&vp, g_k);   float* pk   = (float*)vp;
    cudaGetSymbolAddress(&vp, g_v);   float* pv   = (float*)vp;
    cudaGetSymbolAddress(&vp, g_ctx); float* pctx = (float*)vp;
    cudaGetSymbolAddress(&vp, g_tmp); float* ptmp = (float*)vp;

    copy_x_kernel<<<(BLq * DMq / 4) / 256, 256>>>((const float4*)x_in);

    dim3 ggrid(DMq / 64, BLq / 128);   // (4, 64)

    for (int lay = 0; lay < NLq; lay++) {
        const float* WQ = wq + (size_t)lay * DMq * DMq;
        const float* WK = wk + (size_t)lay * DMq * DMq;
        const float* WV = wv + (size_t)lay * DMq * DMq;
        const float* WO = wo + (size_t)lay * DMq * DMq;

        gemm128_kernel<<<ggrid, 256>>>(px, WQ, bq + (size_t)lay * DMq, pq);
        gemm128_kernel<<<ggrid, 256>>>(px, WK, bk + (size_t)lay * DMq, pk);
        gemm128_kernel<<<ggrid, 256>>>(px, WV, bv + (size_t)lay * DMq, pv);

        // layer key = fold_in(key(42), lay); randint lower_bits from split(rkey)[1]
        uint32_t k0, k1, s0, s1;
        tf2x32(0u, 42u, 0u, (uint32_t)lay, k0, k1);
        tf2x32(k0, k1, 0u, 1u, s0, s1);
        rng_idx_kernel<<<(Lq * Uq + 255) / 256, 256>>>(s0, s1);

        compute_M_kernel<<<(Bq * Hq * Lq) / 256, 256>>>();
        topk_kernel<<<Bq * Hq, 256>>>();
        vmean_part_kernel<<<dim3(32, Bq), DMq>>>();
        vmean_final_kernel<<<Bq, DMq>>>();
        attn_kernel<<<Bq * Hq * Uq, 256>>>();
        ctx_fill_kernel<<<(BLq * DMq) / 256, 256>>>();
        ctx_scatter_kernel<<<(Bq * Hq * Uq * Eq + 255) / 256, 256>>>();

        gemm128_kernel<<<ggrid, 256>>>(pctx, WO, bo + (size_t)lay * DMq, ptmp);
        post_kernel<<<BLq, DMq>>>(c1w + (size_t)lay * INTERq * DMq,
                                  c1b + (size_t)lay * INTERq,
                                  c2w + (size_t)lay * DMq * INTERq,
                                  c2b + (size_t)lay * DMq,
                                  ln1g + (size_t)lay * DMq,
                                  ln1b + (size_t)lay * DMq,
                                  ln2g + (size_t)lay * DMq,
                                  ln2b + (size_t)lay * DMq);

        if (lay < NLq - 1) {
            wtrans_kernel<<<DMq, DMq>>>(dcw + (size_t)lay * DMq * DMq * 3);
            convgemm_kernel<<<ggrid, 256>>>(dcb + (size_t)lay * DMq);
            bn_part_kernel<<<32, DMq>>>();
            bn_final_kernel<<<1, DMq>>>();
            bn_elu_kernel<<<(BLq * DMq) / 256, 256>>>(
                bng + (size_t)lay * DMq,
                bnb + (size_t)lay * DMq);
        }
    }

    final_ln_kernel<<<BLq, DMq>>>(fng, fnb, out);
}

// round 6
// speedup vs baseline: 2.7735x; 1.2526x over previous
#include <cuda_runtime.h>
#include <cuda_bf16.h>
#include <math.h>
#include <stdint.h>

// Problem constants
#define Bq   4
#define Lq   2048
#define DMq  256
#define Hq   8
#define Eq   32
#define NLq  3
#define INTERq 16
#define Uq   40
#define BLq  (Bq*Lq)     // 8192
#define QB   5           // queries per attn block (40 = 8 groups * 5)

// ---------------- scratch (device globals; no allocation allowed) -------------
__device__ float g_x[BLq*DMq];
__device__ float g_q[BLq*DMq];
__device__ float g_k[BLq*DMq];
__device__ float g_v[BLq*DMq];
__device__ float g_ctx[BLq*DMq];
__device__ float g_tmp[BLq*DMq];
__device__ float g_wt[3*DMq*DMq];       // transposed conv weights [t][o][i]
__device__ int   g_idx[Lq*Uq];
__device__ float g_M[Bq*Hq*Lq];
__device__ int   g_top[Bq*Hq*Uq];
__device__ float g_vmean[Bq*DMq];
__device__ float g_vpart[Bq*32*DMq];
__device__ float g_upd[Bq*Hq*Uq*Eq];
__device__ float g_bnp1[32*DMq];
__device__ float g_bnp2[32*DMq];
__device__ float g_bnm[DMq];
__device__ float g_bnv[DMq];

// ---------------- Threefry-2x32 (matches JAX) ---------------------------------
__host__ __device__ inline void tf2x32(uint32_t k0, uint32_t k1,
                                       uint32_t x0, uint32_t x1,
                                       uint32_t& o0, uint32_t& o1) {
    uint32_t ks[3];
    ks[0] = k0; ks[1] = k1; ks[2] = k0 ^ k1 ^ 0x1BD11BDAu;
    x0 += ks[0]; x1 += ks[1];
    const int R0[4] = {13, 15, 26, 6};
    const int R1[4] = {17, 29, 16, 24};
    #pragma unroll
    for (int i = 0; i < 5; i++) {
        #pragma unroll
        for (int j = 0; j < 4; j++) {
            int r = (i & 1) ? R1[j] : R0[j];
            x0 += x1;
            x1 = (x1 << r) | (x1 >> (32 - r));
            x1 ^= x0;
        }
        x0 += ks[(i + 1) % 3];
        x1 += ks[(i + 2) % 3] + (uint32_t)(i + 1);
    }
    o0 = x0; o1 = x1;
}

__global__ void rng_idx_kernel(uint32_t s0, uint32_t s1) {
    int f = blockIdx.x * blockDim.x + threadIdx.x;
    if (f < Lq * Uq) {
        uint32_t o0, o1;
        tf2x32(s0, s1, 0u, (uint32_t)f, o0, o1);
        g_idx[f] = (int)((o0 ^ o1) & 2047u);
    }
}

// ---------------- copy input x (vectorized) -----------------------------------
__global__ void copy_x_kernel(const float4* __restrict__ src) {
    int t = blockIdx.x * blockDim.x + threadIdx.x;
    if (t < BLq * DMq / 4) ((float4*)g_x)[t] = src[t];
}

// ---------------- fp32 GEMM 128x128, 8x8/thread, reg-prefetch -----------------
// grid (2, 64) = 128 blocks, 256 threads. C = A(Mx256) * W(Nx256)^T + bias
__global__ __launch_bounds__(256)
void gemm_big_kernel(const float* __restrict__ A,
                     const float* __restrict__ W,
                     const float* __restrict__ bias,
                     float* __restrict__ C) {
    __shared__ float As[8][132];
    __shared__ float Ws[8][132];
    int tid = threadIdx.x;
    int m0 = blockIdx.y * 128;
    int n0 = blockIdx.x * 128;
    int lr = tid >> 1;                 // 0..127
    int lc = (tid & 1) << 2;           // 0 or 4
    int ty = tid >> 4;                 // 0..15
    int tx = tid & 15;                 // 0..15
    const float* Ap = A + (size_t)(m0 + lr) * DMq + lc;
    const float* Wp = W + (size_t)(n0 + lr) * DMq + lc;

    float4 av = *(const float4*)Ap;
    float4 wv = *(const float4*)Wp;
    float acc[8][8];
    #pragma unroll
    for (int i = 0; i < 8; i++)
        #pragma unroll
        for (int j = 0; j < 8; j++) acc[i][j] = 0.f;

    for (int k0 = 0; k0 < DMq; k0 += 8) {
        As[lc+0][lr] = av.x; As[lc+1][lr] = av.y; As[lc+2][lr] = av.z; As[lc+3][lr] = av.w;
        Ws[lc+0][lr] = wv.x; Ws[lc+1][lr] = wv.y; Ws[lc+2][lr] = wv.z; Ws[lc+3][lr] = wv.w;
        __syncthreads();
        if (k0 + 8 < DMq) {
            av = *(const float4*)(Ap + k0 + 8);
            wv = *(const float4*)(Wp + k0 + 8);
        }
        #pragma unroll
        for (int kk = 0; kk < 8; kk++) {
            float a[8], b[8];
            float4 a0 = *(const float4*)&As[kk][ty * 8];
            float4 a1 = *(const float4*)&As[kk][ty * 8 + 4];
            float4 b0 = *(const float4*)&Ws[kk][tx * 8];
            float4 b1 = *(const float4*)&Ws[kk][tx * 8 + 4];
            a[0]=a0.x; a[1]=a0.y; a[2]=a0.z; a[3]=a0.w;
            a[4]=a1.x; a[5]=a1.y; a[6]=a1.z; a[7]=a1.w;
            b[0]=b0.x; b[1]=b0.y; b[2]=b0.z; b[3]=b0.w;
            b[4]=b1.x; b[5]=b1.y; b[6]=b1.z; b[7]=b1.w;
            #pragma unroll
            for (int i = 0; i < 8; i++)
                #pragma unroll
                for (int j = 0; j < 8; j++) acc[i][j] += a[i] * b[j];
        }
        __syncthreads();
    }
    #pragma unroll
    for (int i = 0; i < 8; i++) {
        int m = m0 + ty * 8 + i;
        #pragma unroll
        for (int j = 0; j < 8; j++) {
            int n = n0 + tx * 8 + j;
            C[(size_t)m * DMq + n] = acc[i][j] + bias[n];
        }
    }
}

// ---------------- conv weight transpose: dcw[o][i][t] -> g_wt[t][o][i] --------
__global__ void wtrans_kernel(const float* __restrict__ dcw) {
    int o = blockIdx.x;
    int i = threadIdx.x;
    #pragma unroll
    for (int t = 0; t < 3; t++)
        g_wt[t * DMq * DMq + o * DMq + i] = dcw[(size_t)o * DMq * 3 + i * 3 + t];
}

// ---------------- conv as 3-tap GEMM (circular rows), 128x128 tile ------------
__global__ __launch_bounds__(256)
void convgemm_kernel(const float* __restrict__ cb) {
    __shared__ float As[8][132];
    __shared__ float Ws[8][132];
    int tid = threadIdx.x;
    int m0 = blockIdx.y * 128;
    int n0 = blockIdx.x * 128;
    int lr = tid >> 1;
    int lc = (tid & 1) << 2;
    int ty = tid >> 4;
    int tx = tid & 15;

    int m = m0 + lr;
    int b = m >> 11;
    int l = m & 2047;
    size_t rowoff[3];
    #pragma unroll
    for (int t = 0; t < 3; t++)
        rowoff[t] = ((size_t)((b << 11) | ((l + t + 2047) & 2047))) * DMq + lc;

    float acc[8][8];
    #pragma unroll
    for (int i = 0; i < 8; i++)
        #pragma unroll
        for (int j = 0; j < 8; j++) acc[i][j] = 0.f;

    // flattened 96 chunk-iterations (3 taps x 32 k-chunks)
    float4 av = *(const float4*)&g_x[rowoff[0]];
    float4 wv = *(const float4*)&g_wt[(size_t)(n0 + lr) * DMq + lc];
    for (int kt = 0; kt < 96; kt++) {
        As[lc+0][lr] = av.x; As[lc+1][lr] = av.y; As[lc+2][lr] = av.z; As[lc+3][lr] = av.w;
        Ws[lc+0][lr] = wv.x; Ws[lc+1][lr] = wv.y; Ws[lc+2][lr] = wv.z; Ws[lc+3][lr] = wv.w;
        __syncthreads();
        if (kt + 1 < 96) {
            int t2 = (kt + 1) >> 5;
            int k2 = ((kt + 1) & 31) << 3;
            av = *(const float4*)&g_x[rowoff[t2] + k2];
            wv = *(const float4*)&g_wt[(size_t)t2 * DMq * DMq + (size_t)(n0 + lr) * DMq + k2 + lc];
        }
        #pragma unroll
        for (int kk = 0; kk < 8; kk++) {
            float a[8], bb[8];
            float4 a0 = *(const float4*)&As[kk][ty * 8];
            float4 a1 = *(const float4*)&As[kk][ty * 8 + 4];
            float4 b0 = *(const float4*)&Ws[kk][tx * 8];
            float4 b1 = *(const float4*)&Ws[kk][tx * 8 + 4];
            a[0]=a0.x; a[1]=a0.y; a[2]=a0.z; a[3]=a0.w;
            a[4]=a1.x; a[5]=a1.y; a[6]=a1.z; a[7]=a1.w;
            bb[0]=b0.x; bb[1]=b0.y; bb[2]=b0.z; bb[3]=b0.w;
            bb[4]=b1.x; bb[5]=b1.y; bb[6]=b1.z; bb[7]=b1.w;
            #pragma unroll
            for (int i = 0; i < 8; i++)
                #pragma unroll
                for (int j = 0; j < 8; j++) acc[i][j] += a[i] * bb[j];
        }
        __syncthreads();
    }
    #pragma unroll
    for (int i = 0; i < 8; i++) {
        int mm = m0 + ty * 8 + i;
        #pragma unroll
        for (int j = 0; j < 8; j++) {
            int n = n0 + tx * 8 + j;
            g_tmp[(size_t)mm * DMq + n] = acc[i][j] + cb[n];
        }
    }
}

// ---------------- M: 4 threads per query, coalesced gather --------------------
__global__ void compute_M_kernel() {
    int t = blockIdx.x * blockDim.x + threadIdx.x;      // B*H*L*4
    int q = t >> 2;
    int j = t & 3;
    int l = q & (Lq - 1);
    int bh = q >> 11;
    int h = bh & (Hq - 1);
    int b = bh >> 3;
    const float4* qp = (const float4*)(g_q + ((size_t)(b * Lq + l) * DMq + h * Eq + j * 8));
    float4 q0 = qp[0], q1 = qp[1];
    float mx = -INFINITY, sm = 0.f;
    #pragma unroll 4
    for (int s = 0; s < Uq; s++) {
        int kl = g_idx[l * Uq + s];
        const float4* kp = (const float4*)(g_k + ((size_t)(b * Lq + kl) * DMq + h * Eq + j * 8));
        float4 k0 = kp[0], k1 = kp[1];
        float d = q0.x*k0.x + q0.y*k0.y + q0.z*k0.z + q0.w*k0.w
                + q1.x*k1.x + q1.y*k1.y + q1.z*k1.z + q1.w*k1.w;
        d += __shfl_xor_sync(0xffffffffu, d, 1);
        d += __shfl_xor_sync(0xffffffffu, d, 2);
        mx = fmaxf(mx, d);
        sm += d;
    }
    if (j == 0) g_M[q] = mx - sm * (1.0f / (float)Lq);
}

// ---------------- top-k (top 40 of 2048, smaller-index tiebreak) --------------
__global__ void topk_kernel() {
    __shared__ float sv[Lq];
    __shared__ float rv[256];
    __shared__ int   ri[256];
    int bh = blockIdx.x;
    const float* Mrow = g_M + (size_t)bh * Lq;
    for (int i = threadIdx.x; i < Lq; i += 256) sv[i] = Mrow[i];
    __syncthreads();
    for (int it = 0; it < Uq; it++) {
        float best = -INFINITY; int bi = Lq;
        for (int i = threadIdx.x; i < Lq; i += 256) {
            float v = sv[i];
            if (v > best) { best = v; bi = i; }
        }
        rv[threadIdx.x] = best; ri[threadIdx.x] = bi;
        __syncthreads();
        for (int s = 128; s > 0; s >>= 1) {
            if (threadIdx.x < s) {
                float v2 = rv[threadIdx.x + s]; int i2 = ri[threadIdx.x + s];
                if (v2 > rv[threadIdx.x] ||
                    (v2 == rv[threadIdx.x] && i2 < ri[threadIdx.x])) {
                    rv[threadIdx.x] = v2; ri[threadIdx.x] = i2;
                }
            }
            __syncthreads();
        }
        if (threadIdx.x == 0) {
            g_top[bh * Uq + it] = ri[0];
            sv[ri[0]] = -INFINITY;
        }
        __syncthreads();
    }
}

// ---------------- mean of v over L: two-stage ---------------------------------
__global__ void vmean_part_kernel() {
    int b = blockIdx.y;
    int chunk = blockIdx.x;            // 0..31, 64 rows each
    int d = threadIdx.x;
    float s = 0.f;
    int r0 = chunk * 64;
    for (int r = 0; r < 64; r++)
        s += g_v[(size_t)(b * Lq + r0 + r) * DMq + d];
    g_vpart[(size_t)(b * 32 + chunk) * DMq + d] = s;
}

__global__ void vmean_final_kernel() {
    int b = blockIdx.x;
    int d = threadIdx.x;
    float s = 0.f;
    for (int c = 0; c < 32; c++) s += g_vpart[(size_t)(b * 32 + c) * DMq + d];
    g_vmean[b * DMq + d] = s * (1.0f / (float)Lq);
}

// ---------------- attention: QB queries per block, K/V reused -----------------
// grid = B*H*8 (8 groups of QB queries), 256 threads
__global__ __launch_bounds__(256)
void attn_kernel() {
    __shared__ float sp[QB][Lq];           // 40KB
    __shared__ float qs[QB][Eq];
    __shared__ float redm[QB][8];
    __shared__ float reds[QB][8];
    __shared__ float outacc[8][QB][Eq];    // 5KB
    const float SCALE = 0.17677669529663687f;
    int blk = blockIdx.x;
    int grp = blk & 7;
    int bh = blk >> 3;
    int h = bh & (Hq - 1);
    int b = bh >> 3;
    int tid = threadIdx.x;
    int lane = tid & 31;
    int wid = tid >> 5;

    // load the QB query rows
    for (int i = tid; i < QB * Eq; i += 256) {
        int qq = i >> 5, e = i & 31;
        int lqi = g_top[bh * Uq + grp * QB + qq];
        qs[qq][e] = g_q[(size_t)(b * Lq + lqi) * DMq + h * Eq + e];
    }
    __syncthreads();

    // pass 1: scores for all QB queries
    float lmax[QB];
    #pragma unroll
    for (int qq = 0; qq < QB; qq++) lmax[qq] = -INFINITY;
    for (int kk = tid; kk < Lq; kk += 256) {
        const float4* k4 = (const float4*)(g_k + ((size_t)(b * Lq + kk) * DMq + h * Eq));
        float4 kv[8];
        #pragma unroll
        for (int j = 0; j < 8; j++) kv[j] = k4[j];
        #pragma unroll
        for (int qq = 0; qq < QB; qq++) {
            const float4* q4 = (const float4*)qs[qq];
            float d = 0.f;
            #pragma unroll
            for (int j = 0; j < 8; j++) {
                float4 qv = q4[j];
                d += qv.x*kv[j].x + qv.y*kv[j].y + qv.z*kv[j].z + qv.w*kv[j].w;
            }
            d *= SCALE;
            sp[qq][kk] = d;
            lmax[qq] = fmaxf(lmax[qq], d);
        }
    }
    #pragma unroll
    for (int qq = 0; qq < QB; qq++) {
        float v = lmax[qq];
        #pragma unroll
        for (int off = 16; off > 0; off >>= 1)
            v = fmaxf(v, __shfl_xor_sync(0xffffffffu, v, off));
        if (lane == 0) redm[qq][wid] = v;
    }
    __syncthreads();
    float gmax[QB];
    #pragma unroll
    for (int qq = 0; qq < QB; qq++) {
        float v = redm[qq][0];
        #pragma unroll
        for (int w = 1; w < 8; w++) v = fmaxf(v, redm[qq][w]);
        gmax[qq] = v;
    }

    // pass: exponentiate + sum
    float lsum[QB];
    #pragma unroll
    for (int qq = 0; qq < QB; qq++) lsum[qq] = 0.f;
    for (int kk = tid; kk < Lq; kk += 256) {
        #pragma unroll
        for (int qq = 0; qq < QB; qq++) {
            float p = expf(sp[qq][kk] - gmax[qq]);
            sp[qq][kk] = p;
            lsum[qq] += p;
        }
    }
    #pragma unroll
    for (int qq = 0; qq < QB; qq++) {
        float v = lsum[qq];
        #pragma unroll
        for (int off = 16; off > 0; off >>= 1)
            v += __shfl_xor_sync(0xffffffffu, v, off);
        if (lane == 0) reds[qq][wid] = v;
    }
    __syncthreads();
    float ginv[QB];
    #pragma unroll
    for (int qq = 0; qq < QB; qq++) {
        float v = 0.f;
        #pragma unroll
        for (int w = 0; w < 8; w++) v += reds[qq][w];
        ginv[qq] = 1.0f / v;
    }

    // pass 2: PV — warp w handles keys kk % 8 == w, lane = dim e (coalesced V)
    {
        int e = lane;
        float acc[QB];
        #pragma unroll
        for (int qq = 0; qq < QB; qq++) acc[qq] = 0.f;
        for (int kk = wid; kk < Lq; kk += 8) {
            float vv = g_v[(size_t)(b * Lq + kk) * DMq + h * Eq + e];
            #pragma unroll
            for (int qq = 0; qq < QB; qq++)
                acc[qq] += sp[qq][kk] * vv;
        }
        #pragma unroll
        for (int qq = 0; qq < QB; qq++) outacc[wid][qq][e] = acc[qq];
    }
    __syncthreads();
    if (tid < QB * Eq) {
        int qq = tid >> 5, e = tid & 31;
        float s = 0.f;
        #pragma unroll
        for (int w = 0; w < 8; w++) s += outacc[w][qq][e];
        g_upd[((size_t)bh * Uq + grp * QB + qq) * Eq + e] = s * ginv[qq];
    }
}

// ---------------- ctx assembly ------------------------------------------------
__global__ void ctx_fill_kernel() {
    int t = blockIdx.x * blockDim.x + threadIdx.x;
    if (t >= BLq * DMq) return;
    int d = t % DMq;
    int bl = t / DMq;
    int b = bl / Lq;
    g_ctx[t] = g_vmean[b * DMq + d];
}

__global__ void ctx_scatter_kernel() {
    int t = blockIdx.x * blockDim.x + threadIdx.x;
    if (t >= Bq * Hq * Uq * Eq) return;
    int e = t % Eq;
    int rest = t / Eq;
    int u = rest % Uq;
    int bh = rest / Uq;
    int h = bh % Hq;
    int b = bh / Hq;
    int l = g_top[bh * Uq + u];
    g_ctx[(size_t)(b * Lq + l) * DMq + h * Eq + e] = g_upd[t];
}

// ---------------- fused: LN1(x+tmp) -> FFN -> +res -> LN2, in-place on g_x ----
__global__ void post_kernel(const float* __restrict__ c1w,
                            const float* __restrict__ c1b,
                            const float* __restrict__ c2w,
                            const float* __restrict__ c2b,
                            const float* __restrict__ g1,
                            const float* __restrict__ b1,
                            const float* __restrict__ g2,
                            const float* __restrict__ b2) {
    __shared__ float xs[DMq];
    __shared__ float ys[INTERq];
    __shared__ float red[256];
    int row = blockIdx.x;
    int d = threadIdx.x;
    size_t off = (size_t)row * DMq + d;
    float v = g_x[off] + g_tmp[off];
    red[d] = v;
    __syncthreads();
    for (int s = 128; s > 0; s >>= 1) {
        if (d < s) red[d] += red[d + s];
        __syncthreads();
    }
    float m = red[0] * (1.0f / (float)DMq);
    __syncthreads();
    float c = v - m;
    red[d] = c * c;
    __syncthreads();
    for (int s = 128; s > 0; s >>= 1) {
        if (d < s) red[d] += red[d + s];
        __syncthreads();
    }
    float var = red[0] * (1.0f / (float)DMq);
    float x1 = c * rsqrtf(var + 1e-5f) * g1[d] + b1[d];
    __syncthreads();
    xs[d] = x1;
    __syncthreads();
    if (d < INTERq) {
        float a = c1b[d];
        const float* wrow = c1w + (size_t)d * DMq;
        for (int k = 0; k < DMq; k++) a += xs[k] * wrow[k];
        ys[d] = fmaxf(a, 0.f);
    }
    __syncthreads();
    float a2 = c2b[d];
    const float* w2 = c2w + (size_t)d * INTERq;
    #pragma unroll
    for (int f = 0; f < INTERq; f++) a2 += ys[f] * w2[f];
    float v2 = x1 + a2;
    red[d] = v2;
    __syncthreads();
    for (int s = 128; s > 0; s >>= 1) {
        if (d < s) red[d] += red[d + s];
        __syncthreads();
    }
    float m2 = red[0] * (1.0f / (float)DMq);
    __syncthreads();
    float c2 = v2 - m2;
    red[d] = c2 * c2;
    __syncthreads();
    for (int s = 128; s > 0; s >>= 1) {
        if (d < s) red[d] += red[d + s];
        __syncthreads();
    }
    float var2 = red[0] * (1.0f / (float)DMq);
    g_x[off] = c2 * rsqrtf(var2 + 1e-5f) * g2[d] + b2[d];
}

// ---------------- batchnorm stats (deterministic, fixed order) ----------------
__global__ void bn_part_kernel() {
    int chunk = blockIdx.x;
    int d = threadIdx.x;
    float s = 0.f, s2 = 0.f;
    int r0 = chunk * 256;
    for (int r = 0; r < 256; r++) {
        float v = g_tmp[(size_t)(r0 + r) * DMq + d];
        s += v; s2 += v * v;
    }
    g_bnp1[chunk * DMq + d] = s;
    g_bnp2[chunk * DMq + d] = s2;
}

__global__ void bn_final_kernel() {
    int d = threadIdx.x;
    float s = 0.f, s2 = 0.f;
    for (int c = 0; c < 32; c++) {
        s  += g_bnp1[c * DMq + d];
        s2 += g_bnp2[c * DMq + d];
    }
    float m = s * (1.0f / (float)BLq);
    g_bnm[d] = m;
    g_bnv[d] = s2 * (1.0f / (float)BLq) - m * m;
}

__global__ void bn_elu_kernel(const float* __restrict__ gam,
                              const float* __restrict__ bet) {
    int t = blockIdx.x * blockDim.x + threadIdx.x;
    if (t >= BLq * DMq) return;
    int d = t % DMq;
    float y = (g_tmp[t] - g_bnm[d]) * rsqrtf(g_bnv[d] + 1e-5f) * gam[d] + bet[d];
    g_x[t] = (y > 0.f) ? y : expm1f(y);
}

// ---------------- final LayerNorm into d_out ----------------------------------
__global__ void final_ln_kernel(const float* __restrict__ gam,
                                const float* __restrict__ bet,
                                float* __restrict__ out) {
    __shared__ float red[256];
    int row = blockIdx.x;
    int d = threadIdx.x;
    size_t off = (size_t)row * DMq + d;
    float v = g_x[off];
    red[d] = v;
    __syncthreads();
    for (int s = 128; s > 0; s >>= 1) {
        if (d < s) red[d] += red[d + s];
        __syncthreads();
    }
    float m = red[0] * (1.0f / (float)DMq);
    __syncthreads();
    float c = v - m;
    red[d] = c * c;
    __syncthreads();
    for (int s = 128; s > 0; s >>= 1) {
        if (d < s) red[d] += red[d + s];
        __syncthreads();
    }
    float var = red[0] * (1.0f / (float)DMq);
    out[off] = c * rsqrtf(var + 1e-5f) * gam[d] + bet[d];
}

// ---------------- host driver -------------------------------------------------
extern "C" void kernel_launch(void* const* d_in, const int* in_sizes, int n_in,
                              void* d_out, int out_size) {
    const float* x_in = (const float*)d_in[0];
    const float* wq   = (const float*)d_in[1];
    const float* bq   = (const float*)d_in[2];
    const float* wk   = (const float*)d_in[3];
    const float* bk   = (const float*)d_in[4];
    const float* wv   = (const float*)d_in[5];
    const float* bv   = (const float*)d_in[6];
    const float* wo   = (const float*)d_in[7];
    const float* bo   = (const float*)d_in[8];
    const float* c1w  = (const float*)d_in[9];
    const float* c1b  = (const float*)d_in[10];
    const float* c2w  = (const float*)d_in[11];
    const float* c2b  = (const float*)d_in[12];
    const float* ln1g = (const float*)d_in[13];
    const float* ln1b = (const float*)d_in[14];
    const float* ln2g = (const float*)d_in[15];
    const float* ln2b = (const float*)d_in[16];
    const float* dcw  = (const float*)d_in[17];
    const float* dcb  = (const float*)d_in[18];
    const float* bng  = (const float*)d_in[19];
    const float* bnb  = (const float*)d_in[20];
    const float* fng  = (const float*)d_in[21];
    const float* fnb  = (const float*)d_in[22];
    float* out = (float*)d_out;

    // Real device addresses of __device__ globals (host-shadow/ATS trap on GB300)
    void *vp;
    cudaGetSymbolAddress(&vp, g_x);   float* px   = (float*)vp;
    cudaGetSymbolAddress(&vp, g_q);   float* pq   = (float*)vp;
    cudaGetSymbolAddress(&vp, g_k);   float* pk   = (float*)vp;
    cudaGetSymbolAddress(&vp, g_v);   float* pv   = (float*)vp;
    cudaGetSymbolAddress(&vp, g_ctx); float* pctx = (float*)vp;
    cudaGetSymbolAddress(&vp, g_tmp); float* ptmp = (float*)vp;

    copy_x_kernel<<<(BLq * DMq / 4) / 256, 256>>>((const float4*)x_in);

    dim3 ggrid(DMq / 128, BLq / 128);   // (2, 64) = 128 blocks

    for (int lay = 0; lay < NLq; lay++) {
        const float* WQ = wq + (size_t)lay * DMq * DMq;
        const float* WK = wk + (size_t)lay * DMq * DMq;
        const float* WV = wv + (size_t)lay * DMq * DMq;
        const float* WO = wo + (size_t)lay * DMq * DMq;

        gemm_big_kernel<<<ggrid, 256>>>(px, WQ, bq + (size_t)lay * DMq, pq);
        gemm_big_kernel<<<ggrid, 256>>>(px, WK, bk + (size_t)lay * DMq, pk);
        gemm_big_kernel<<<ggrid, 256>>>(px, WV, bv + (size_t)lay * DMq, pv);

        // layer key = fold_in(key(42), lay); randint lower_bits from split(rkey)[1]
        uint32_t k0, k1, s0, s1;
        tf2x32(0u, 42u, 0u, (uint32_t)lay, k0, k1);
        tf2x32(k0, k1, 0u, 1u, s0, s1);
        rng_idx_kernel<<<(Lq * Uq + 255) / 256, 256>>>(s0, s1);

        compute_M_kernel<<<(Bq * Hq * Lq * 4) / 256, 256>>>();
        topk_kernel<<<Bq * Hq, 256>>>();
        vmean_part_kernel<<<dim3(32, Bq), DMq>>>();
        vmean_final_kernel<<<Bq, DMq>>>();
        attn_kernel<<<Bq * Hq * 8, 256>>>();
        ctx_fill_kernel<<<(BLq * DMq) / 256, 256>>>();
        ctx_scatter_kernel<<<(Bq * Hq * Uq * Eq + 255) / 256, 256>>>();

        gemm_big_kernel<<<ggrid, 256>>>(pctx, WO, bo + (size_t)lay * DMq, ptmp);
        post_kernel<<<BLq, DMq>>>(c1w + (size_t)lay * INTERq * DMq,
                                  c1b + (size_t)lay * INTERq,
                                  c2w + (size_t)lay * DMq * INTERq,
                                  c2b + (size_t)lay * DMq,
                                  ln1g + (size_t)lay * DMq,
                                  ln1b + (size_t)lay * DMq,
                                  ln2g + (size_t)lay * DMq,
                                  ln2b + (size_t)lay * DMq);

        if (lay < NLq - 1) {
            wtrans_kernel<<<DMq, DMq>>>(dcw + (size_t)lay * DMq * DMq * 3);
            convgemm_kernel<<<ggrid, 256>>>(dcb + (size_t)lay * DMq);
            bn_part_kernel<<<32, DMq>>>();
            bn_final_kernel<<<1, DMq>>>();
            bn_elu_kernel<<<(BLq * DMq) / 256, 256>>>(
                bng + (size_t)lay * DMq,
                bnb + (size_t)lay * DMq);
        }
    }

    final_ln_kernel<<<BLq, DMq>>>(fng, fnb, out);
}

// round 7
// speedup vs baseline: 3.4569x; 1.2464x over previous
#include <cuda_runtime.h>
#include <cuda_bf16.h>
#include <math.h>
#include <stdint.h>

// Problem constants
#define Bq   4
#define Lq   2048
#define DMq  256
#define Hq   8
#define Eq   32
#define NLq  3
#define INTERq 16
#define Uq   40
#define BLq  (Bq*Lq)     // 8192
#define QB   5           // queries per attn block

// ---------------- scratch (device globals; no allocation allowed) -------------
__device__ float g_x[BLq*DMq];
__device__ float g_q[BLq*DMq];
__device__ float g_k[BLq*DMq];
__device__ float g_v[BLq*DMq];
__device__ float g_ctx[BLq*DMq];
__device__ float g_tmp[BLq*DMq];
__device__ __nv_bfloat16 g_ahi[BLq*DMq];
__device__ __nv_bfloat16 g_alo[BLq*DMq];
__device__ __nv_bfloat16 g_whi[12*DMq*DMq];   // [lay*4+slot][n][k]
__device__ __nv_bfloat16 g_wlo[12*DMq*DMq];
__device__ __nv_bfloat16 g_cwhi[6*DMq*DMq];   // [lay*3+t][o][i]
__device__ __nv_bfloat16 g_cwlo[6*DMq*DMq];
__device__ int   g_idx[Lq*Uq];
__device__ float g_M[Bq*Hq*Lq];
__device__ int   g_top[Bq*Hq*Uq];
__device__ float g_vmean[Bq*DMq];
__device__ float g_vpart[Bq*32*DMq];
__device__ float g_upd[Bq*Hq*Uq*Eq];
__device__ float g_bnp1[32*DMq];
__device__ float g_bnp2[32*DMq];
__device__ float g_bnm[DMq];
__device__ float g_bnv[DMq];

// ---------------- Threefry-2x32 (matches JAX) ---------------------------------
__host__ __device__ inline void tf2x32(uint32_t k0, uint32_t k1,
                                       uint32_t x0, uint32_t x1,
                                       uint32_t& o0, uint32_t& o1) {
    uint32_t ks[3];
    ks[0] = k0; ks[1] = k1; ks[2] = k0 ^ k1 ^ 0x1BD11BDAu;
    x0 += ks[0]; x1 += ks[1];
    const int R0[4] = {13, 15, 26, 6};
    const int R1[4] = {17, 29, 16, 24};
    #pragma unroll
    for (int i = 0; i < 5; i++) {
        #pragma unroll
        for (int j = 0; j < 4; j++) {
            int r = (i & 1) ? R1[j] : R0[j];
            x0 += x1;
            x1 = (x1 << r) | (x1 >> (32 - r));
            x1 ^= x0;
        }
        x0 += ks[(i + 1) % 3];
        x1 += ks[(i + 2) % 3] + (uint32_t)(i + 1);
    }
    o0 = x0; o1 = x1;
}

__global__ void rng_idx_kernel(uint32_t s0, uint32_t s1) {
    int f = blockIdx.x * blockDim.x + threadIdx.x;
    if (f < Lq * Uq) {
        uint32_t o0, o1;
        tf2x32(s0, s1, 0u, (uint32_t)f, o0, o1);
        g_idx[f] = (int)((o0 ^ o1) & 2047u);
    }
}

// ---------------- copy input x -------------------------------------------------
__global__ void copy_x_kernel(const float4* __restrict__ src) {
    int t = blockIdx.x * blockDim.x + threadIdx.x;
    if (t < BLq * DMq / 4) ((float4*)g_x)[t] = src[t];
}

// ---------------- split fp32 -> bf16 hi/lo ------------------------------------
__global__ void split_a_kernel(const float* __restrict__ src) {
    int t = blockIdx.x * blockDim.x + threadIdx.x;
    if (t < BLq * DMq) {
        float v = src[t];
        __nv_bfloat16 h = __float2bfloat16(v);
        g_ahi[t] = h;
        g_alo[t] = __float2bfloat16(v - __bfloat162float(h));
    }
}

// weights: src is [NL][DM][DM]; dst slot layout [lay*4+slot][n][k]
__global__ void split_w_kernel(const float* __restrict__ src, int slot) {
    int t = blockIdx.x * blockDim.x + threadIdx.x;
    if (t < NLq * DMq * DMq) {
        int lay = t >> 16;
        int r = t & 65535;
        float v = src[t];
        __nv_bfloat16 h = __float2bfloat16(v);
        int d = (((lay << 2) + slot) << 16) | r;
        g_whi[d] = h;
        g_wlo[d] = __float2bfloat16(v - __bfloat162float(h));
    }
}

// conv weights: dcw[(NL-1)][o][i][t] -> g_cw[(lay*3+t)][o][i]
__global__ void split_cw_kernel(const float* __restrict__ dcw) {
    int t = blockIdx.x * blockDim.x + threadIdx.x;
    if (t < (NLq - 1) * 3 * DMq * DMq) {
        int lay = t / (3 * 65536);
        int rem = t % (3 * 65536);
        int tap = rem >> 16;
        int oi = rem & 65535;
        int o = oi >> 8;
        int i = oi & 255;
        float v = dcw[(size_t)lay * 3 * 65536 + o * 768 + i * 3 + tap];
        __nv_bfloat16 h = __float2bfloat16(v);
        g_cwhi[t] = h;
        g_cwlo[t] = __float2bfloat16(v - __bfloat162float(h));
    }
}

// ---------------- split-bf16 tensor-core GEMM ---------------------------------
#define MMA_BF16(c, a, b) \
    asm volatile("mma.sync.aligned.m16n8k16.row.col.f32.bf16.bf16.f32 " \
        "{%0,%1,%2,%3}, {%4,%5,%6,%7}, {%8,%9}, {%0,%1,%2,%3};" \
        : "+f"((c)[0]), "+f"((c)[1]), "+f"((c)[2]), "+f"((c)[3]) \
        : "r"((a)[0]), "r"((a)[1]), "r"((a)[2]), "r"((a)[3]), \
          "r"((b)[0]), "r"((b)[1]))

// C[8192][256] = A*W^T + bias;  A from g_ahi/g_alo, W slot in g_whi/g_wlo.
// grid (2, 64), 256 threads (8 warps: wm = w&1 (2 x m64), wn = w>>1 (4 x n32)).
__global__ __launch_bounds__(256)
void gemm_bf16_kernel(int slot, const float* __restrict__ bias,
                      float* __restrict__ C) {
    __shared__ __nv_bfloat16 sAh[128*24], sAl[128*24], sBh[128*24], sBl[128*24];
    int tid = threadIdx.x;
    int m0 = blockIdx.y * 128, n0 = blockIdx.x * 128;
    int lr = tid >> 1, lh = tid & 1;
    int w = tid >> 5, lane = tid & 31;
    int wm = w & 1, wn = w >> 1;
    int grp = lane >> 2, tig = lane & 3;

    const __nv_bfloat16* Wh = g_whi + (size_t)slot * DMq * DMq;
    const __nv_bfloat16* Wl = g_wlo + (size_t)slot * DMq * DMq;
    size_t aoff = (size_t)(m0 + lr) * DMq + lh * 8;
    size_t boff = (size_t)(n0 + lr) * DMq + lh * 8;
    int sidx = lr * 24 + lh * 8;

    float acc[4][4][4];
    #pragma unroll
    for (int i = 0; i < 4; i++)
        #pragma unroll
        for (int j = 0; j < 4; j++)
            #pragma unroll
            for (int q = 0; q < 4; q++) acc[i][j][q] = 0.f;

    uint4 rah = *(const uint4*)(g_ahi + aoff);
    uint4 ral = *(const uint4*)(g_alo + aoff);
    uint4 rbh = *(const uint4*)(Wh + boff);
    uint4 rbl = *(const uint4*)(Wl + boff);

    for (int c = 0; c < 16; c++) {
        *(uint4*)(sAh + sidx) = rah;
        *(uint4*)(sAl + sidx) = ral;
        *(uint4*)(sBh + sidx) = rbh;
        *(uint4*)(sBl + sidx) = rbl;
        __syncthreads();
        if (c + 1 < 16) {
            rah = *(const uint4*)(g_ahi + aoff + (c + 1) * 16);
            ral = *(const uint4*)(g_alo + aoff + (c + 1) * 16);
            rbh = *(const uint4*)(Wh + boff + (c + 1) * 16);
            rbl = *(const uint4*)(Wl + boff + (c + 1) * 16);
        }
        uint32_t bh[4][2], bl[4][2];
        #pragma unroll
        for (int nf = 0; nf < 4; nf++) {
            int n = wn * 32 + nf * 8 + grp;
            bh[nf][0] = *(const uint32_t*)(sBh + n * 24 + tig * 2);
            bh[nf][1] = *(const uint32_t*)(sBh + n * 24 + tig * 2 + 8);
            bl[nf][0] = *(const uint32_t*)(sBl + n * 24 + tig * 2);
            bl[nf][1] = *(const uint32_t*)(sBl + n * 24 + tig * 2 + 8);
        }
        #pragma unroll
        for (int mf = 0; mf < 4; mf++) {
            int r = wm * 64 + mf * 16 + grp;
            uint32_t ah[4], al[4];
            ah[0] = *(const uint32_t*)(sAh + r * 24 + tig * 2);
            ah[1] = *(const uint32_t*)(sAh + (r + 8) * 24 + tig * 2);
            ah[2] = *(const uint32_t*)(sAh + r * 24 + tig * 2 + 8);
            ah[3] = *(const uint32_t*)(sAh + (r + 8) * 24 + tig * 2 + 8);
            al[0] = *(const uint32_t*)(sAl + r * 24 + tig * 2);
            al[1] = *(const uint32_t*)(sAl + (r + 8) * 24 + tig * 2);
            al[2] = *(const uint32_t*)(sAl + r * 24 + tig * 2 + 8);
            al[3] = *(const uint32_t*)(sAl + (r + 8) * 24 + tig * 2 + 8);
            #pragma unroll
            for (int nf = 0; nf < 4; nf++) {
                MMA_BF16(acc[mf][nf], ah, bh[nf]);
                MMA_BF16(acc[mf][nf], ah, bl[nf]);
                MMA_BF16(acc[mf][nf], al, bh[nf]);
            }
        }
        __syncthreads();
    }

    #pragma unroll
    for (int mf = 0; mf < 4; mf++) {
        int r0 = m0 + wm * 64 + mf * 16 + grp;
        #pragma unroll
        for (int nf = 0; nf < 4; nf++) {
            int c0 = n0 + wn * 32 + nf * 8 + tig * 2;
            float2 v0 = {acc[mf][nf][0] + bias[c0], acc[mf][nf][1] + bias[c0 + 1]};
            float2 v1 = {acc[mf][nf][2] + bias[c0], acc[mf][nf][3] + bias[c0 + 1]};
            *(float2*)&C[(size_t)r0 * DMq + c0] = v0;
            *(float2*)&C[(size_t)(r0 + 8) * DMq + c0] = v1;
        }
    }
}

// ---------------- conv as 3-tap split-bf16 GEMM -------------------------------
__global__ __launch_bounds__(256)
void convgemm_bf16_kernel(int lay, const float* __restrict__ cb) {
    __shared__ __nv_bfloat16 sAh[128*24], sAl[128*24], sBh[128*24], sBl[128*24];
    int tid = threadIdx.x;
    int m0 = blockIdx.y * 128, n0 = blockIdx.x * 128;
    int lr = tid >> 1, lh = tid & 1;
    int w = tid >> 5, lane = tid & 31;
    int wm = w & 1, wn = w >> 1;
    int grp = lane >> 2, tig = lane & 3;

    int m = m0 + lr;
    int b = m >> 11;
    int l = m & 2047;
    size_t aoff[3];
    #pragma unroll
    for (int t = 0; t < 3; t++)
        aoff[t] = (size_t)((b << 11) | ((l + t + 2047) & 2047)) * DMq + lh * 8;
    const __nv_bfloat16* Wh3 = g_cwhi + (size_t)(lay * 3) * DMq * DMq;
    const __nv_bfloat16* Wl3 = g_cwlo + (size_t)(lay * 3) * DMq * DMq;
    size_t boff = (size_t)(n0 + lr) * DMq + lh * 8;
    int sidx = lr * 24 + lh * 8;

    float acc[4][4][4];
    #pragma unroll
    for (int i = 0; i < 4; i++)
        #pragma unroll
        for (int j = 0; j < 4; j++)
            #pragma unroll
            for (int q = 0; q < 4; q++) acc[i][j][q] = 0.f;

    uint4 rah = *(const uint4*)(g_ahi + aoff[0]);
    uint4 ral = *(const uint4*)(g_alo + aoff[0]);
    uint4 rbh = *(const uint4*)(Wh3 + boff);
    uint4 rbl = *(const uint4*)(Wl3 + boff);

    for (int kt = 0; kt < 48; kt++) {
        *(uint4*)(sAh + sidx) = rah;
        *(uint4*)(sAl + sidx) = ral;
        *(uint4*)(sBh + sidx) = rbh;
        *(uint4*)(sBl + sidx) = rbl;
        __syncthreads();
        if (kt + 1 < 48) {
            int t2 = (kt + 1) >> 4;
            int c2 = ((kt + 1) & 15) * 16;
            rah = *(const uint4*)(g_ahi + aoff[t2] + c2);
            ral = *(const uint4*)(g_alo + aoff[t2] + c2);
            rbh = *(const uint4*)(Wh3 + (size_t)t2 * DMq * DMq + boff + c2);
            rbl = *(const uint4*)(Wl3 + (size_t)t2 * DMq * DMq + boff + c2);
        }
        uint32_t bh[4][2], bl[4][2];
        #pragma unroll
        for (int nf = 0; nf < 4; nf++) {
            int n = wn * 32 + nf * 8 + grp;
            bh[nf][0] = *(const uint32_t*)(sBh + n * 24 + tig * 2);
            bh[nf][1] = *(const uint32_t*)(sBh + n * 24 + tig * 2 + 8);
            bl[nf][0] = *(const uint32_t*)(sBl + n * 24 + tig * 2);
            bl[nf][1] = *(const uint32_t*)(sBl + n * 24 + tig * 2 + 8);
        }
        #pragma unroll
        for (int mf = 0; mf < 4; mf++) {
            int r = wm * 64 + mf * 16 + grp;
            uint32_t ah[4], al[4];
            ah[0] = *(const uint32_t*)(sAh + r * 24 + tig * 2);
            ah[1] = *(const uint32_t*)(sAh + (r + 8) * 24 + tig * 2);
            ah[2] = *(const uint32_t*)(sAh + r * 24 + tig * 2 + 8);
            ah[3] = *(const uint32_t*)(sAh + (r + 8) * 24 + tig * 2 + 8);
            al[0] = *(const uint32_t*)(sAl + r * 24 + tig * 2);
            al[1] = *(const uint32_t*)(sAl + (r + 8) * 24 + tig * 2);
            al[2] = *(const uint32_t*)(sAl + r * 24 + tig * 2 + 8);
            al[3] = *(const uint32_t*)(sAl + (r + 8) * 24 + tig * 2 + 8);
            #pragma unroll
            for (int nf = 0; nf < 4; nf++) {
                MMA_BF16(acc[mf][nf], ah, bh[nf]);
                MMA_BF16(acc[mf][nf], ah, bl[nf]);
                MMA_BF16(acc[mf][nf], al, bh[nf]);
            }
        }
        __syncthreads();
    }

    #pragma unroll
    for (int mf = 0; mf < 4; mf++) {
        int r0 = m0 + wm * 64 + mf * 16 + grp;
        #pragma unroll
        for (int nf = 0; nf < 4; nf++) {
            int c0 = n0 + wn * 32 + nf * 8 + tig * 2;
            float2 v0 = {acc[mf][nf][0] + cb[c0], acc[mf][nf][1] + cb[c0 + 1]};
            float2 v1 = {acc[mf][nf][2] + cb[c0], acc[mf][nf][3] + cb[c0 + 1]};
            *(float2*)&g_tmp[(size_t)r0 * DMq + c0] = v0;
            *(float2*)&g_tmp[(size_t)(r0 + 8) * DMq + c0] = v1;
        }
    }
}

// ---------------- M: 4 threads per query, coalesced gather --------------------
__global__ void compute_M_kernel() {
    int t = blockIdx.x * blockDim.x + threadIdx.x;
    int q = t >> 2;
    int j = t & 3;
    int l = q & (Lq - 1);
    int bh = q >> 11;
    int h = bh & (Hq - 1);
    int b = bh >> 3;
    const float4* qp = (const float4*)(g_q + ((size_t)(b * Lq + l) * DMq + h * Eq + j * 8));
    float4 q0 = qp[0], q1 = qp[1];
    float mx = -INFINITY, sm = 0.f;
    #pragma unroll 4
    for (int s = 0; s < Uq; s++) {
        int kl = g_idx[l * Uq + s];
        const float4* kp = (const float4*)(g_k + ((size_t)(b * Lq + kl) * DMq + h * Eq + j * 8));
        float4 k0 = kp[0], k1 = kp[1];
        float d = q0.x*k0.x + q0.y*k0.y + q0.z*k0.z + q0.w*k0.w
                + q1.x*k1.x + q1.y*k1.y + q1.z*k1.z + q1.w*k1.w;
        d += __shfl_xor_sync(0xffffffffu, d, 1);
        d += __shfl_xor_sync(0xffffffffu, d, 2);
        mx = fmaxf(mx, d);
        sm += d;
    }
    if (j == 0) g_M[q] = mx - sm * (1.0f / (float)Lq);
}

// ---------------- top-k via full bitonic sort (value desc, index asc) ---------
__device__ inline uint32_t fsortable(float f) {
    uint32_t u = __float_as_uint(f);
    return (u & 0x80000000u) ? ~u : (u | 0x80000000u);
}

__global__ __launch_bounds__(256)
void topk_kernel() {
    __shared__ unsigned long long key[Lq];
    int bh = blockIdx.x;
    int tid = threadIdx.x;
    const float* Mrow = g_M + (size_t)bh * Lq;
    for (int i = tid; i < Lq; i += 256) {
        uint32_t s = fsortable(Mrow[i]);
        key[i] = ((unsigned long long)(~s) << 32) | (uint32_t)i;
    }
    for (int k = 2; k <= Lq; k <<= 1) {
        for (int j = k >> 1; j > 0; j >>= 1) {
            __syncthreads();
            for (int i = tid; i < Lq; i += 256) {
                int l = i ^ j;
                if (l > i) {
                    unsigned long long a = key[i], c = key[l];
                    bool asc = ((i & k) == 0);
                    if ((a > c) == asc) { key[i] = c; key[l] = a; }
                }
            }
        }
    }
    __syncthreads();
    if (tid < Uq) g_top[bh * Uq + tid] = (int)(key[tid] & 0xffffffffu);
}

// ---------------- mean of v over L: two-stage ---------------------------------
__global__ void vmean_part_kernel() {
    int b = blockIdx.y;
    int chunk = blockIdx.x;
    int d = threadIdx.x;
    float s = 0.f;
    int r0 = chunk * 64;
    for (int r = 0; r < 64; r++)
        s += g_v[(size_t)(b * Lq + r0 + r) * DMq + d];
    g_vpart[(size_t)(b * 32 + chunk) * DMq + d] = s;
}

__global__ void vmean_final_kernel() {
    int b = blockIdx.x;
    int d = threadIdx.x;
    float s = 0.f;
    for (int c = 0; c < 32; c++) s += g_vpart[(size_t)(b * 32 + c) * DMq + d];
    g_vmean[b * DMq + d] = s * (1.0f / (float)Lq);
}

// ---------------- attention: QB queries per block -----------------------------
__global__ __launch_bounds__(256)
void attn_kernel() {
    __shared__ float sp[QB][Lq];
    __shared__ float qs[QB][Eq];
    __shared__ float redm[QB][8];
    __shared__ float reds[QB][8];
    __shared__ float outacc[8][QB][Eq];
    const float SCALE = 0.17677669529663687f;
    int blk = blockIdx.x;
    int grp = blk & 7;
    int bh = blk >> 3;
    int h = bh & (Hq - 1);
    int b = bh >> 3;
    int tid = threadIdx.x;
    int lane = tid & 31;
    int wid = tid >> 5;

    for (int i = tid; i < QB * Eq; i += 256) {
        int qq = i >> 5, e = i & 31;
        int lqi = g_top[bh * Uq + grp * QB + qq];
        qs[qq][e] = g_q[(size_t)(b * Lq + lqi) * DMq + h * Eq + e];
    }
    __syncthreads();

    float lmax[QB];
    #pragma unroll
    for (int qq = 0; qq < QB; qq++) lmax[qq] = -INFINITY;
    for (int kk = tid; kk < Lq; kk += 256) {
        const float4* k4 = (const float4*)(g_k + ((size_t)(b * Lq + kk) * DMq + h * Eq));
        float4 kv[8];
        #pragma unroll
        for (int j = 0; j < 8; j++) kv[j] = k4[j];
        #pragma unroll
        for (int qq = 0; qq < QB; qq++) {
            const float4* q4 = (const float4*)qs[qq];
            float d = 0.f;
            #pragma unroll
            for (int j = 0; j < 8; j++) {
                float4 qv = q4[j];
                d += qv.x*kv[j].x + qv.y*kv[j].y + qv.z*kv[j].z + qv.w*kv[j].w;
            }
            d *= SCALE;
            sp[qq][kk] = d;
            lmax[qq] = fmaxf(lmax[qq], d);
        }
    }
    #pragma unroll
    for (int qq = 0; qq < QB; qq++) {
        float v = lmax[qq];
        #pragma unroll
        for (int off = 16; off > 0; off >>= 1)
            v = fmaxf(v, __shfl_xor_sync(0xffffffffu, v, off));
        if (lane == 0) redm[qq][wid] = v;
    }
    __syncthreads();
    float gmax[QB];
    #pragma unroll
    for (int qq = 0; qq < QB; qq++) {
        float v = redm[qq][0];
        #pragma unroll
        for (int w2 = 1; w2 < 8; w2++) v = fmaxf(v, redm[qq][w2]);
        gmax[qq] = v;
    }

    float lsum[QB];
    #pragma unroll
    for (int qq = 0; qq < QB; qq++) lsum[qq] = 0.f;
    for (int kk = tid; kk < Lq; kk += 256) {
        #pragma unroll
        for (int qq = 0; qq < QB; qq++) {
            float p = expf(sp[qq][kk] - gmax[qq]);
            sp[qq][kk] = p;
            lsum[qq] += p;
        }
    }
    #pragma unroll
    for (int qq = 0; qq < QB; qq++) {
        float v = lsum[qq];
        #pragma unroll
        for (int off = 16; off > 0; off >>= 1)
            v += __shfl_xor_sync(0xffffffffu, v, off);
        if (lane == 0) reds[qq][wid] = v;
    }
    __syncthreads();
    float ginv[QB];
    #pragma unroll
    for (int qq = 0; qq < QB; qq++) {
        float v = 0.f;
        #pragma unroll
        for (int w2 = 0; w2 < 8; w2++) v += reds[qq][w2];
        ginv[qq] = 1.0f / v;
    }

    {
        int e = lane;
        float acc[QB];
        #pragma unroll
        for (int qq = 0; qq < QB; qq++) acc[qq] = 0.f;
        for (int kk = wid; kk < Lq; kk += 8) {
            float vv = g_v[(size_t)(b * Lq + kk) * DMq + h * Eq + e];
            #pragma unroll
            for (int qq = 0; qq < QB; qq++)
                acc[qq] += sp[qq][kk] * vv;
        }
        #pragma unroll
        for (int qq = 0; qq < QB; qq++) outacc[wid][qq][e] = acc[qq];
    }
    __syncthreads();
    if (tid < QB * Eq) {
        int qq = tid >> 5, e = tid & 31;
        float s = 0.f;
        #pragma unroll
        for (int w2 = 0; w2 < 8; w2++) s += outacc[w2][qq][e];
        g_upd[((size_t)bh * Uq + grp * QB + qq) * Eq + e] = s * ginv[qq];
    }
}

// ---------------- ctx assembly ------------------------------------------------
__global__ void ctx_fill_kernel() {
    int t = blockIdx.x * blockDim.x + threadIdx.x;
    if (t >= BLq * DMq) return;
    int d = t % DMq;
    int bl = t / DMq;
    int b = bl / Lq;
    g_ctx[t] = g_vmean[b * DMq + d];
}

__global__ void ctx_scatter_kernel() {
    int t = blockIdx.x * blockDim.x + threadIdx.x;
    if (t >= Bq * Hq * Uq * Eq) return;
    int e = t % Eq;
    int rest = t / Eq;
    int u = rest % Uq;
    int bh = rest / Uq;
    int h = bh % Hq;
    int b = bh / Hq;
    int l = g_top[bh * Uq + u];
    g_ctx[(size_t)(b * Lq + l) * DMq + h * Eq + e] = g_upd[t];
}

// ---------------- fused: LN1(x+tmp) -> FFN -> +res -> LN2 ---------------------
__global__ void post_kernel(const float* __restrict__ c1w,
                            const float* __restrict__ c1b,
                            const float* __restrict__ c2w,
                            const float* __restrict__ c2b,
                            const float* __restrict__ g1,
                            const float* __restrict__ b1,
                            const float* __restrict__ g2,
                            const float* __restrict__ b2) {
    __shared__ float xs[DMq];
    __shared__ float ys[INTERq];
    __shared__ float red[256];
    int row = blockIdx.x;
    int d = threadIdx.x;
    size_t off = (size_t)row * DMq + d;
    float v = g_x[off] + g_tmp[off];
    red[d] = v;
    __syncthreads();
    for (int s = 128; s > 0; s >>= 1) {
        if (d < s) red[d] += red[d + s];
        __syncthreads();
    }
    float m = red[0] * (1.0f / (float)DMq);
    __syncthreads();
    float c = v - m;
    red[d] = c * c;
    __syncthreads();
    for (int s = 128; s > 0; s >>= 1) {
        if (d < s) red[d] += red[d + s];
        __syncthreads();
    }
    float var = red[0] * (1.0f / (float)DMq);
    float x1 = c * rsqrtf(var + 1e-5f) * g1[d] + b1[d];
    __syncthreads();
    xs[d] = x1;
    __syncthreads();
    if (d < INTERq) {
        float a = c1b[d];
        const float* wrow = c1w + (size_t)d * DMq;
        for (int k = 0; k < DMq; k++) a += xs[k] * wrow[k];
        ys[d] = fmaxf(a, 0.f);
    }
    __syncthreads();
    float a2 = c2b[d];
    const float* w2 = c2w + (size_t)d * INTERq;
    #pragma unroll
    for (int f = 0; f < INTERq; f++) a2 += ys[f] * w2[f];
    float v2 = x1 + a2;
    red[d] = v2;
    __syncthreads();
    for (int s = 128; s > 0; s >>= 1) {
        if (d < s) red[d] += red[d + s];
        __syncthreads();
    }
    float m2 = red[0] * (1.0f / (float)DMq);
    __syncthreads();
    float c2 = v2 - m2;
    red[d] = c2 * c2;
    __syncthreads();
    for (int s = 128; s > 0; s >>= 1) {
        if (d < s) red[d] += red[d + s];
        __syncthreads();
    }
    float var2 = red[0] * (1.0f / (float)DMq);
    g_x[off] = c2 * rsqrtf(var2 + 1e-5f) * g2[d] + b2[d];
}

// ---------------- batchnorm stats ---------------------------------------------
__global__ void bn_part_kernel() {
    int chunk = blockIdx.x;
    int d = threadIdx.x;
    float s = 0.f, s2 = 0.f;
    int r0 = chunk * 256;
    for (int r = 0; r < 256; r++) {
        float v = g_tmp[(size_t)(r0 + r) * DMq + d];
        s += v; s2 += v * v;
    }
    g_bnp1[chunk * DMq + d] = s;
    g_bnp2[chunk * DMq + d] = s2;
}

__global__ void bn_final_kernel() {
    int d = threadIdx.x;
    float s = 0.f, s2 = 0.f;
    for (int c = 0; c < 32; c++) {
        s  += g_bnp1[c * DMq + d];
        s2 += g_bnp2[c * DMq + d];
    }
    float m = s * (1.0f / (float)BLq);
    g_bnm[d] = m;
    g_bnv[d] = s2 * (1.0f / (float)BLq) - m * m;
}

__global__ void bn_elu_kernel(const float* __restrict__ gam,
                              const float* __restrict__ bet) {
    int t = blockIdx.x * blockDim.x + threadIdx.x;
    if (t >= BLq * DMq) return;
    int d = t % DMq;
    float y = (g_tmp[t] - g_bnm[d]) * rsqrtf(g_bnv[d] + 1e-5f) * gam[d] + bet[d];
    g_x[t] = (y > 0.f) ? y : expm1f(y);
}

// ---------------- final LayerNorm into d_out ----------------------------------
__global__ void final_ln_kernel(const float* __restrict__ gam,
                                const float* __restrict__ bet,
                                float* __restrict__ out) {
    __shared__ float red[256];
    int row = blockIdx.x;
    int d = threadIdx.x;
    size_t off = (size_t)row * DMq + d;
    float v = g_x[off];
    red[d] = v;
    __syncthreads();
    for (int s = 128; s > 0; s >>= 1) {
        if (d < s) red[d] += red[d + s];
        __syncthreads();
    }
    float m = red[0] * (1.0f / (float)DMq);
    __syncthreads();
    float c = v - m;
    red[d] = c * c;
    __syncthreads();
    for (int s = 128; s > 0; s >>= 1) {
        if (d < s) red[d] += red[d + s];
        __syncthreads();
    }
    float var = red[0] * (1.0f / (float)DMq);
    out[off] = c * rsqrtf(var + 1e-5f) * gam[d] + bet[d];
}

// ---------------- host driver -------------------------------------------------
extern "C" void kernel_launch(void* const* d_in, const int* in_sizes, int n_in,
                              void* d_out, int out_size) {
    const float* x_in = (const float*)d_in[0];
    const float* wq   = (const float*)d_in[1];
    const float* bq   = (const float*)d_in[2];
    const float* wk   = (const float*)d_in[3];
    const float* bk   = (const float*)d_in[4];
    const float* wv   = (const float*)d_in[5];
    const float* bv   = (const float*)d_in[6];
    const float* wo   = (const float*)d_in[7];
    const float* bo   = (const float*)d_in[8];
    const float* c1w  = (const float*)d_in[9];
    const float* c1b  = (const float*)d_in[10];
    const float* c2w  = (const float*)d_in[11];
    const float* c2b  = (const float*)d_in[12];
    const float* ln1g = (const float*)d_in[13];
    const float* ln1b = (const float*)d_in[14];
    const float* ln2g = (const float*)d_in[15];
    const float* ln2b = (const float*)d_in[16];
    const float* dcw  = (const float*)d_in[17];
    const float* dcb  = (const float*)d_in[18];
    const float* bng  = (const float*)d_in[19];
    const float* bnb  = (const float*)d_in[20];
    const float* fng  = (const float*)d_in[21];
    const float* fnb  = (const float*)d_in[22];
    float* out = (float*)d_out;

    // Real device addresses (host-shadow/ATS trap on GB300)
    void *vp;
    cudaGetSymbolAddress(&vp, g_x);   float* px   = (float*)vp;
    cudaGetSymbolAddress(&vp, g_q);   float* pq   = (float*)vp;
    cudaGetSymbolAddress(&vp, g_k);   float* pk   = (float*)vp;
    cudaGetSymbolAddress(&vp, g_v);   float* pv   = (float*)vp;
    cudaGetSymbolAddress(&vp, g_ctx); float* pctx = (float*)vp;
    cudaGetSymbolAddress(&vp, g_tmp); float* ptmp = (float*)vp;

    copy_x_kernel<<<(BLq * DMq / 4) / 256, 256>>>((const float4*)x_in);

    // one-time weight splits
    int nw = NLq * DMq * DMq;
    split_w_kernel<<<(nw + 255) / 256, 256>>>(wq, 0);
    split_w_kernel<<<(nw + 255) / 256, 256>>>(wk, 1);
    split_w_kernel<<<(nw + 255) / 256, 256>>>(wv, 2);
    split_w_kernel<<<(nw + 255) / 256, 256>>>(wo, 3);
    int ncw = (NLq - 1) * 3 * DMq * DMq;
    split_cw_kernel<<<(ncw + 255) / 256, 256>>>(dcw);

    dim3 ggrid(DMq / 128, BLq / 128);   // (2, 64)

    for (int lay = 0; lay < NLq; lay++) {
        split_a_kernel<<<(BLq * DMq) / 256, 256>>>(px);
        gemm_bf16_kernel<<<ggrid, 256>>>(lay * 4 + 0, bq + (size_t)lay * DMq, pq);
        gemm_bf16_kernel<<<ggrid, 256>>>(lay * 4 + 1, bk + (size_t)lay * DMq, pk);
        gemm_bf16_kernel<<<ggrid, 256>>>(lay * 4 + 2, bv + (size_t)lay * DMq, pv);

        uint32_t k0, k1, s0, s1;
        tf2x32(0u, 42u, 0u, (uint32_t)lay, k0, k1);
        tf2x32(k0, k1, 0u, 1u, s0, s1);
        rng_idx_kernel<<<(Lq * Uq + 255) / 256, 256>>>(s0, s1);

        compute_M_kernel<<<(Bq * Hq * Lq * 4) / 256, 256>>>();
        topk_kernel<<<Bq * Hq, 256>>>();
        vmean_part_kernel<<<dim3(32, Bq), DMq>>>();
        vmean_final_kernel<<<Bq, DMq>>>();
        attn_kernel<<<Bq * Hq * 8, 256>>>();
        ctx_fill_kernel<<<(BLq * DMq) / 256, 256>>>();
        ctx_scatter_kernel<<<(Bq * Hq * Uq * Eq + 255) / 256, 256>>>();

        split_a_kernel<<<(BLq * DMq) / 256, 256>>>(pctx);
        gemm_bf16_kernel<<<ggrid, 256>>>(lay * 4 + 3, bo + (size_t)lay * DMq, ptmp);

        post_kernel<<<BLq, DMq>>>(c1w + (size_t)lay * INTERq * DMq,
                                  c1b + (size_t)lay * INTERq,
                                  c2w + (size_t)lay * DMq * INTERq,
                                  c2b + (size_t)lay * DMq,
                                  ln1g + (size_t)lay * DMq,
                                  ln1b + (size_t)lay * DMq,
                                  ln2g + (size_t)lay * DMq,
                                  ln2b + (size_t)lay * DMq);

        if (lay < NLq - 1) {
            split_a_kernel<<<(BLq * DMq) / 256, 256>>>(px);
            convgemm_bf16_kernel<<<ggrid, 256>>>(lay, dcb + (size_t)lay * DMq);
            bn_part_kernel<<<32, DMq>>>();
            bn_final_kernel<<<1, DMq>>>();
            bn_elu_kernel<<<(BLq * DMq) / 256, 256>>>(
                bng + (size_t)lay * DMq,
                bnb + (size_t)lay * DMq);
        }
    }

    final_ln_kernel<<<BLq, DMq>>>(fng, fnb, out);
}

// round 9
// speedup vs baseline: 5.0571x; 1.4629x over previous
#include <cuda_runtime.h>
#include <cuda_bf16.h>
#include <math.h>
#include <stdint.h>

// Problem constants
#define Bq   4
#define Lq   2048
#define DMq  256
#define Hq   8
#define Eq   32
#define NLq  3
#define INTERq 16
#define Uq   40
#define BLq  (Bq*Lq)     // 8192
#define QB   5

// ---------------- scratch (device globals; no allocation allowed) -------------
__device__ float g_x[BLq*DMq];
__device__ float g_q[BLq*DMq];
__device__ float g_k[BLq*DMq];
__device__ float g_v[BLq*DMq];
__device__ float g_tmp[BLq*DMq];
__device__ __nv_bfloat16 g_ahi[BLq*DMq];
__device__ __nv_bfloat16 g_alo[BLq*DMq];
__device__ __nv_bfloat16 g_whi[12*DMq*DMq];   // [lay*4+slot][n][k]
__device__ __nv_bfloat16 g_wlo[12*DMq*DMq];
__device__ __nv_bfloat16 g_cwhi[6*DMq*DMq];   // [lay*3+t][o][i]
__device__ __nv_bfloat16 g_cwlo[6*DMq*DMq];
__device__ float g_wot[DMq*DMq];              // WO^T for current layer
__device__ float g_ybase[Bq*DMq];             // vmean @ WO^T + bo
__device__ int   g_selmap[Bq*Hq*Lq];
__device__ int   g_idx[Lq*Uq];
__device__ float g_M[Bq*Hq*Lq];
__device__ int   g_top[Bq*Hq*Uq];
__device__ float g_vmean[Bq*DMq];
__device__ float g_vpart[Bq*32*DMq];
__device__ float g_upd[Bq*Hq*Uq*Eq];
__device__ float g_bnp1[256*DMq];
__device__ float g_bnp2[256*DMq];
__device__ float g_bnm[DMq];
__device__ float g_bnv[DMq];

// ---------------- Threefry-2x32 (matches JAX) ---------------------------------
__host__ __device__ inline void tf2x32(uint32_t k0, uint32_t k1,
                                       uint32_t x0, uint32_t x1,
                                       uint32_t& o0, uint32_t& o1) {
    uint32_t ks[3];
    ks[0] = k0; ks[1] = k1; ks[2] = k0 ^ k1 ^ 0x1BD11BDAu;
    x0 += ks[0]; x1 += ks[1];
    const int R0[4] = {13, 15, 26, 6};
    const int R1[4] = {17, 29, 16, 24};
    #pragma unroll
    for (int i = 0; i < 5; i++) {
        #pragma unroll
        for (int j = 0; j < 4; j++) {
            int r = (i & 1) ? R1[j] : R0[j];
            x0 += x1;
            x1 = (x1 << r) | (x1 >> (32 - r));
            x1 ^= x0;
        }
        x0 += ks[(i + 1) % 3];
        x1 += ks[(i + 2) % 3] + (uint32_t)(i + 1);
    }
    o0 = x0; o1 = x1;
}

__global__ void rng_idx_kernel(uint32_t s0, uint32_t s1) {
    int f = blockIdx.x * blockDim.x + threadIdx.x;
    if (f < Lq * Uq) {
        uint32_t o0, o1;
        tf2x32(s0, s1, 0u, (uint32_t)f, o0, o1);
        g_idx[f] = (int)((o0 ^ o1) & 2047u);
    }
}

// ---------------- block-sum helper (256 threads) -------------------------------
__device__ __forceinline__ float bsum256(float v, float* s8, int lane, int wid) {
    #pragma unroll
    for (int o = 16; o > 0; o >>= 1) v += __shfl_xor_sync(0xffffffffu, v, o);
    if (lane == 0) s8[wid] = v;
    __syncthreads();
    float r = s8[0] + s8[1] + s8[2] + s8[3] + s8[4] + s8[5] + s8[6] + s8[7];
    __syncthreads();
    return r;
}

// ---------------- copy input x + bf16 split ------------------------------------
__global__ void copy_x_kernel(const float* __restrict__ src) {
    int t = blockIdx.x * blockDim.x + threadIdx.x;
    if (t < BLq * DMq) {
        float v = src[t];
        g_x[t] = v;
        __nv_bfloat16 h = __float2bfloat16(v);
        g_ahi[t] = h;
        g_alo[t] = __float2bfloat16(v - __bfloat162float(h));
    }
}

// weights: src is [NL][DM][DM]; dst slot layout [lay*4+slot][n][k]
__global__ void split_w_kernel(const float* __restrict__ src, int slot) {
    int t = blockIdx.x * blockDim.x + threadIdx.x;
    if (t < NLq * DMq * DMq) {
        int lay = t >> 16;
        int r = t & 65535;
        float v = src[t];
        __nv_bfloat16 h = __float2bfloat16(v);
        int d = (((lay << 2) + slot) << 16) | r;
        g_whi[d] = h;
        g_wlo[d] = __float2bfloat16(v - __bfloat162float(h));
    }
}

// conv weights: dcw[(NL-1)][o][i][t] -> g_cw[(lay*3+t)][o][i]
__global__ void split_cw_kernel(const float* __restrict__ dcw) {
    int t = blockIdx.x * blockDim.x + threadIdx.x;
    if (t < (NLq - 1) * 3 * DMq * DMq) {
        int lay = t / (3 * 65536);
        int rem = t % (3 * 65536);
        int tap = rem >> 16;
        int oi = rem & 65535;
        int o = oi >> 8;
        int i = oi & 255;
        float v = dcw[(size_t)lay * 3 * 65536 + o * 768 + i * 3 + tap];
        __nv_bfloat16 h = __float2bfloat16(v);
        g_cwhi[t] = h;
        g_cwlo[t] = __float2bfloat16(v - __bfloat162float(h));
    }
}

// ---------------- split-bf16 tensor-core GEMM ----------------------------------
#define MMA_BF16(c, a, b) \
    asm volatile("mma.sync.aligned.m16n8k16.row.col.f32.bf16.bf16.f32 " \
        "{%0,%1,%2,%3}, {%4,%5,%6,%7}, {%8,%9}, {%0,%1,%2,%3};" \
        : "+f"((c)[0]), "+f"((c)[1]), "+f"((c)[2]), "+f"((c)[3]) \
        : "r"((a)[0]), "r"((a)[1]), "r"((a)[2]), "r"((a)[3]), \
          "r"((b)[0]), "r"((b)[1]))

__global__ __launch_bounds__(256)
void gemm_bf16_kernel(int slot, const float* __restrict__ bias,
                      float* __restrict__ C) {
    __shared__ __nv_bfloat16 sAh[128*24], sAl[128*24], sBh[128*24], sBl[128*24];
    int tid = threadIdx.x;
    int m0 = blockIdx.y * 128, n0 = blockIdx.x * 128;
    int lr = tid >> 1, lh = tid & 1;
    int w = tid >> 5, lane = tid & 31;
    int wm = w & 1, wn = w >> 1;
    int grp = lane >> 2, tig = lane & 3;

    const __nv_bfloat16* Wh = g_whi + (size_t)slot * DMq * DMq;
    const __nv_bfloat16* Wl = g_wlo + (size_t)slot * DMq * DMq;
    size_t aoff = (size_t)(m0 + lr) * DMq + lh * 8;
    size_t boff = (size_t)(n0 + lr) * DMq + lh * 8;
    int sidx = lr * 24 + lh * 8;

    float acc[4][4][4];
    #pragma unroll
    for (int i = 0; i < 4; i++)
        #pragma unroll
        for (int j = 0; j < 4; j++)
            #pragma unroll
            for (int q = 0; q < 4; q++) acc[i][j][q] = 0.f;

    uint4 rah = *(const uint4*)(g_ahi + aoff);
    uint4 ral = *(const uint4*)(g_alo + aoff);
    uint4 rbh = *(const uint4*)(Wh + boff);
    uint4 rbl = *(const uint4*)(Wl + boff);

    for (int c = 0; c < 16; c++) {
        *(uint4*)(sAh + sidx) = rah;
        *(uint4*)(sAl + sidx) = ral;
        *(uint4*)(sBh + sidx) = rbh;
        *(uint4*)(sBl + sidx) = rbl;
        __syncthreads();
        if (c + 1 < 16) {
            rah = *(const uint4*)(g_ahi + aoff + (c + 1) * 16);
            ral = *(const uint4*)(g_alo + aoff + (c + 1) * 16);
            rbh = *(const uint4*)(Wh + boff + (c + 1) * 16);
            rbl = *(const uint4*)(Wl + boff + (c + 1) * 16);
        }
        uint32_t bh[4][2], bl[4][2];
        #pragma unroll
        for (int nf = 0; nf < 4; nf++) {
            int n = wn * 32 + nf * 8 + grp;
            bh[nf][0] = *(const uint32_t*)(sBh + n * 24 + tig * 2);
            bh[nf][1] = *(const uint32_t*)(sBh + n * 24 + tig * 2 + 8);
            bl[nf][0] = *(const uint32_t*)(sBl + n * 24 + tig * 2);
            bl[nf][1] = *(const uint32_t*)(sBl + n * 24 + tig * 2 + 8);
        }
        #pragma unroll
        for (int mf = 0; mf < 4; mf++) {
            int r = wm * 64 + mf * 16 + grp;
            uint32_t ah[4], al[4];
            ah[0] = *(const uint32_t*)(sAh + r * 24 + tig * 2);
            ah[1] = *(const uint32_t*)(sAh + (r + 8) * 24 + tig * 2);
            ah[2] = *(const uint32_t*)(sAh + r * 24 + tig * 2 + 8);
            ah[3] = *(const uint32_t*)(sAh + (r + 8) * 24 + tig * 2 + 8);
            al[0] = *(const uint32_t*)(sAl + r * 24 + tig * 2);
            al[1] = *(const uint32_t*)(sAl + (r + 8) * 24 + tig * 2);
            al[2] = *(const uint32_t*)(sAl + r * 24 + tig * 2 + 8);
            al[3] = *(const uint32_t*)(sAl + (r + 8) * 24 + tig * 2 + 8);
            #pragma unroll
            for (int nf = 0; nf < 4; nf++) {
                MMA_BF16(acc[mf][nf], ah, bh[nf]);
                MMA_BF16(acc[mf][nf], ah, bl[nf]);
                MMA_BF16(acc[mf][nf], al, bh[nf]);
            }
        }
        __syncthreads();
    }

    #pragma unroll
    for (int mf = 0; mf < 4; mf++) {
        int r0 = m0 + wm * 64 + mf * 16 + grp;
        #pragma unroll
        for (int nf = 0; nf < 4; nf++) {
            int c0 = n0 + wn * 32 + nf * 8 + tig * 2;
            float2 v0 = {acc[mf][nf][0] + bias[c0], acc[mf][nf][1] + bias[c0 + 1]};
            float2 v1 = {acc[mf][nf][2] + bias[c0], acc[mf][nf][3] + bias[c0 + 1]};
            *(float2*)&C[(size_t)r0 * DMq + c0] = v0;
            *(float2*)&C[(size_t)(r0 + 8) * DMq + c0] = v1;
        }
    }
}

// ---------------- conv as 3-tap split-bf16 GEMM --------------------------------
__global__ __launch_bounds__(256)
void convgemm_bf16_kernel(int lay, const float* __restrict__ cb) {
    __shared__ __nv_bfloat16 sAh[128*24], sAl[128*24], sBh[128*24], sBl[128*24];
    int tid = threadIdx.x;
    int m0 = blockIdx.y * 128, n0 = blockIdx.x * 128;
    int lr = tid >> 1, lh = tid & 1;
    int w = tid >> 5, lane = tid & 31;
    int wm = w & 1, wn = w >> 1;
    int grp = lane >> 2, tig = lane & 3;

    int m = m0 + lr;
    int b = m >> 11;
    int l = m & 2047;
    size_t aoff[3];
    #pragma unroll
    for (int t = 0; t < 3; t++)
        aoff[t] = (size_t)((b << 11) | ((l + t + 2047) & 2047)) * DMq + lh * 8;
    const __nv_bfloat16* Wh3 = g_cwhi + (size_t)(lay * 3) * DMq * DMq;
    const __nv_bfloat16* Wl3 = g_cwlo + (size_t)(lay * 3) * DMq * DMq;
    size_t boff = (size_t)(n0 + lr) * DMq + lh * 8;
    int sidx = lr * 24 + lh * 8;

    float acc[4][4][4];
    #pragma unroll
    for (int i = 0; i < 4; i++)
        #pragma unroll
        for (int j = 0; j < 4; j++)
            #pragma unroll
            for (int q = 0; q < 4; q++) acc[i][j][q] = 0.f;

    uint4 rah = *(const uint4*)(g_ahi + aoff[0]);
    uint4 ral = *(const uint4*)(g_alo + aoff[0]);
    uint4 rbh = *(const uint4*)(Wh3 + boff);
    uint4 rbl = *(const uint4*)(Wl3 + boff);

    for (int kt = 0; kt < 48; kt++) {
        *(uint4*)(sAh + sidx) = rah;
        *(uint4*)(sAl + sidx) = ral;
        *(uint4*)(sBh + sidx) = rbh;
        *(uint4*)(sBl + sidx) = rbl;
        __syncthreads();
        if (kt + 1 < 48) {
            int t2 = (kt + 1) >> 4;
            int c2 = ((kt + 1) & 15) * 16;
            rah = *(const uint4*)(g_ahi + aoff[t2] + c2);
            ral = *(const uint4*)(g_alo + aoff[t2] + c2);
            rbh = *(const uint4*)(Wh3 + (size_t)t2 * DMq * DMq + boff + c2);
            rbl = *(const uint4*)(Wl3 + (size_t)t2 * DMq * DMq + boff + c2);
        }
        uint32_t bh[4][2], bl[4][2];
        #pragma unroll
        for (int nf = 0; nf < 4; nf++) {
            int n = wn * 32 + nf * 8 + grp;
            bh[nf][0] = *(const uint32_t*)(sBh + n * 24 + tig * 2);
            bh[nf][1] = *(const uint32_t*)(sBh + n * 24 + tig * 2 + 8);
            bl[nf][0] = *(const uint32_t*)(sBl + n * 24 + tig * 2);
            bl[nf][1] = *(const uint32_t*)(sBl + n * 24 + tig * 2 + 8);
        }
        #pragma unroll
        for (int mf = 0; mf < 4; mf++) {
            int r = wm * 64 + mf * 16 + grp;
            uint32_t ah[4], al[4];
            ah[0] = *(const uint32_t*)(sAh + r * 24 + tig * 2);
            ah[1] = *(const uint32_t*)(sAh + (r + 8) * 24 + tig * 2);
            ah[2] = *(const uint32_t*)(sAh + r * 24 + tig * 2 + 8);
            ah[3] = *(const uint32_t*)(sAh + (r + 8) * 24 + tig * 2 + 8);
            al[0] = *(const uint32_t*)(sAl + r * 24 + tig * 2);
            al[1] = *(const uint32_t*)(sAl + (r + 8) * 24 + tig * 2);
            al[2] = *(const uint32_t*)(sAl + r * 24 + tig * 2 + 8);
            al[3] = *(const uint32_t*)(sAl + (r + 8) * 24 + tig * 2 + 8);
            #pragma unroll
            for (int nf = 0; nf < 4; nf++) {
                MMA_BF16(acc[mf][nf], ah, bh[nf]);
                MMA_BF16(acc[mf][nf], ah, bl[nf]);
                MMA_BF16(acc[mf][nf], al, bh[nf]);
            }
        }
        __syncthreads();
    }

    #pragma unroll
    for (int mf = 0; mf < 4; mf++) {
        int r0 = m0 + wm * 64 + mf * 16 + grp;
        #pragma unroll
        for (int nf = 0; nf < 4; nf++) {
            int c0 = n0 + wn * 32 + nf * 8 + tig * 2;
            float2 v0 = {acc[mf][nf][0] + cb[c0], acc[mf][nf][1] + cb[c0 + 1]};
            float2 v1 = {acc[mf][nf][2] + cb[c0], acc[mf][nf][3] + cb[c0 + 1]};
            *(float2*)&g_tmp[(size_t)r0 * DMq + c0] = v0;
            *(float2*)&g_tmp[(size_t)(r0 + 8) * DMq + c0] = v1;
        }
    }
}

// ---------------- M: 4 threads per query ---------------------------------------
__global__ void compute_M_kernel() {
    int t = blockIdx.x * blockDim.x + threadIdx.x;
    int q = t >> 2;
    int j = t & 3;
    int l = q & (Lq - 1);
    int bh = q >> 11;
    int h = bh & (Hq - 1);
    int b = bh >> 3;
    const float4* qp = (const float4*)(g_q + ((size_t)(b * Lq + l) * DMq + h * Eq + j * 8));
    float4 q0 = qp[0], q1 = qp[1];
    float mx = -INFINITY, sm = 0.f;
    #pragma unroll 4
    for (int s = 0; s < Uq; s++) {
        int kl = g_idx[l * Uq + s];
        const float4* kp = (const float4*)(g_k + ((size_t)(b * Lq + kl) * DMq + h * Eq + j * 8));
        float4 k0 = kp[0], k1 = kp[1];
        float d = q0.x*k0.x + q0.y*k0.y + q0.z*k0.z + q0.w*k0.w
                + q1.x*k1.x + q1.y*k1.y + q1.z*k1.z + q1.w*k1.w;
        d += __shfl_xor_sync(0xffffffffu, d, 1);
        d += __shfl_xor_sync(0xffffffffu, d, 2);
        mx = fmaxf(mx, d);
        sm += d;
    }
    if (j == 0) g_M[q] = mx - sm * (1.0f / (float)Lq);
}

// ---------------- top-k via full bitonic sort ----------------------------------
__device__ inline uint32_t fsortable(float f) {
    uint32_t u = __float_as_uint(f);
    return (u & 0x80000000u) ? ~u : (u | 0x80000000u);
}

__global__ __launch_bounds__(512)
void topk_kernel() {
    __shared__ unsigned long long key[Lq];
    int bh = blockIdx.x;
    int tid = threadIdx.x;
    const float* Mrow = g_M + (size_t)bh * Lq;
    for (int i = tid; i < Lq; i += 512) {
        uint32_t s = fsortable(Mrow[i]);
        key[i] = ((unsigned long long)(~s) << 32) | (uint32_t)i;
    }
    for (int k = 2; k <= Lq; k <<= 1) {
        for (int j = k >> 1; j > 0; j >>= 1) {
            __syncthreads();
            for (int i = tid; i < Lq; i += 512) {
                int l = i ^ j;
                if (l > i) {
                    unsigned long long a = key[i], c = key[l];
                    bool asc = ((i & k) == 0);
                    if ((a > c) == asc) { key[i] = c; key[l] = a; }
                }
            }
        }
    }
    __syncthreads();
    if (tid < Uq) g_top[bh * Uq + tid] = (int)(key[tid] & 0xffffffffu);
}

// ---------------- mean of v over L: two-stage ----------------------------------
__global__ void vmean_part_kernel() {
    int b = blockIdx.y;
    int chunk = blockIdx.x;
    int d = threadIdx.x;
    float s = 0.f;
    int r0 = chunk * 64;
    for (int r = 0; r < 64; r++)
        s += g_v[(size_t)(b * Lq + r0 + r) * DMq + d];
    g_vpart[(size_t)(b * 32 + chunk) * DMq + d] = s;
}

__global__ void vmean_final_kernel() {
    int b = blockIdx.x;
    int d = threadIdx.x;
    float s = 0.f;
    for (int c = 0; c < 32; c++) s += g_vpart[(size_t)(b * 32 + c) * DMq + d];
    g_vmean[b * DMq + d] = s * (1.0f / (float)Lq);
}

// ---------------- attention: QB queries per block ------------------------------
__global__ __launch_bounds__(256)
void attn_kernel() {
    __shared__ float sp[QB][Lq];
    __shared__ float qs[QB][Eq];
    __shared__ float redm[QB][8];
    __shared__ float reds[QB][8];
    __shared__ float outacc[8][QB][Eq];
    const float SCALE = 0.17677669529663687f;
    int blk = blockIdx.x;
    int grp = blk & 7;
    int bh = blk >> 3;
    int h = bh & (Hq - 1);
    int b = bh >> 3;
    int tid = threadIdx.x;
    int lane = tid & 31;
    int wid = tid >> 5;

    for (int i = tid; i < QB * Eq; i += 256) {
        int qq = i >> 5, e = i & 31;
        int lqi = g_top[bh * Uq + grp * QB + qq];
        qs[qq][e] = g_q[(size_t)(b * Lq + lqi) * DMq + h * Eq + e];
    }
    __syncthreads();

    float lmax[QB];
    #pragma unroll
    for (int qq = 0; qq < QB; qq++) lmax[qq] = -INFINITY;
    for (int kk = tid; kk < Lq; kk += 256) {
        const float4* k4 = (const float4*)(g_k + ((size_t)(b * Lq + kk) * DMq + h * Eq));
        float4 kv[8];
        #pragma unroll
        for (int j = 0; j < 8; j++) kv[j] = k4[j];
        #pragma unroll
        for (int qq = 0; qq < QB; qq++) {
            const float4* q4 = (const float4*)qs[qq];
            float d = 0.f;
            #pragma unroll
            for (int j = 0; j < 8; j++) {
                float4 qv = q4[j];
                d += qv.x*kv[j].x + qv.y*kv[j].y + qv.z*kv[j].z + qv.w*kv[j].w;
            }
            d *= SCALE;
            sp[qq][kk] = d;
            lmax[qq] = fmaxf(lmax[qq], d);
        }
    }
    #pragma unroll
    for (int qq = 0; qq < QB; qq++) {
        float v = lmax[qq];
        #pragma unroll
        for (int off = 16; off > 0; off >>= 1)
            v = fmaxf(v, __shfl_xor_sync(0xffffffffu, v, off));
        if (lane == 0) redm[qq][wid] = v;
    }
    __syncthreads();
    float gmax[QB];
    #pragma unroll
    for (int qq = 0; qq < QB; qq++) {
        float v = redm[qq][0];
        #pragma unroll
        for (int w2 = 1; w2 < 8; w2++) v = fmaxf(v, redm[qq][w2]);
        gmax[qq] = v;
    }

    float lsum[QB];
    #pragma unroll
    for (int qq = 0; qq < QB; qq++) lsum[qq] = 0.f;
    for (int kk = tid; kk < Lq; kk += 256) {
        #pragma unroll
        for (int qq = 0; qq < QB; qq++) {
            float p = expf(sp[qq][kk] - gmax[qq]);
            sp[qq][kk] = p;
            lsum[qq] += p;
        }
    }
    #pragma unroll
    for (int qq = 0; qq < QB; qq++) {
        float v = lsum[qq];
        #pragma unroll
        for (int off = 16; off > 0; off >>= 1)
            v += __shfl_xor_sync(0xffffffffu, v, off);
        if (lane == 0) reds[qq][wid] = v;
    }
    __syncthreads();
    float ginv[QB];
    #pragma unroll
    for (int qq = 0; qq < QB; qq++) {
        float v = 0.f;
        #pragma unroll
        for (int w2 = 0; w2 < 8; w2++) v += reds[qq][w2];
        ginv[qq] = 1.0f / v;
    }

    {
        int e = lane;
        float acc[QB];
        #pragma unroll
        for (int qq = 0; qq < QB; qq++) acc[qq] = 0.f;
        for (int kk = wid; kk < Lq; kk += 8) {
            float vv = g_v[(size_t)(b * Lq + kk) * DMq + h * Eq + e];
            #pragma unroll
            for (int qq = 0; qq < QB; qq++)
                acc[qq] += sp[qq][kk] * vv;
        }
        #pragma unroll
        for (int qq = 0; qq < QB; qq++) outacc[wid][qq][e] = acc[qq];
    }
    __syncthreads();
    if (tid < QB * Eq) {
        int qq = tid >> 5, e = tid & 31;
        float s = 0.f;
        #pragma unroll
        for (int w2 = 0; w2 < 8; w2++) s += outacc[w2][qq][e];
        g_upd[((size_t)bh * Uq + grp * QB + qq) * Eq + e] = s * ginv[qq];
    }
}

// ---------------- WO special path ----------------------------------------------
// transpose WO -> g_wot
__global__ void wot_kernel(const float* __restrict__ WO) {
    int t = blockIdx.x * blockDim.x + threadIdx.x;   // t = d*256+n
    int d = t >> 8, n = t & 255;
    g_wot[t] = WO[n * DMq + d];
}

// y_b[n] = vmean[b] . WO[n] + bo[n];  grid (4, 8), 256 threads
__global__ void wo_y_kernel(const float* __restrict__ WO,
                            const float* __restrict__ bo) {
    __shared__ float vm[DMq];
    int b = blockIdx.x, ng = blockIdx.y;
    int t = threadIdx.x;
    vm[t] = g_vmean[b * DMq + t];
    __syncthreads();
    int nl = t >> 3, dc = t & 7;
    int n = ng * 32 + nl;
    const float4* w4 = (const float4*)(WO + (size_t)n * DMq + dc * 32);
    float s = 0.f;
    #pragma unroll
    for (int i = 0; i < 8; i++) {
        float4 wv = w4[i];
        int d0 = dc * 32 + i * 4;
        s += vm[d0]*wv.x + vm[d0+1]*wv.y + vm[d0+2]*wv.z + vm[d0+3]*wv.w;
    }
    s += __shfl_down_sync(0xffffffffu, s, 4);
    s += __shfl_down_sync(0xffffffffu, s, 2);
    s += __shfl_down_sync(0xffffffffu, s, 1);
    if (dc == 0) g_ybase[b * DMq + n] = s + bo[n];
}

__global__ void selmap_clear_kernel() {
    int t = blockIdx.x * blockDim.x + threadIdx.x;
    if (t < Bq * Hq * Lq) g_selmap[t] = -1;
}

__global__ void selmap_set_kernel() {
    int t = blockIdx.x * blockDim.x + threadIdx.x;   // B*H*U
    if (t < Bq * Hq * Uq) {
        int u = t % Uq;
        int bh = t / Uq;
        int l = g_top[t];
        g_selmap[bh * Lq + l] = u;
    }
}

// out_row(b,l) = y_b + sum over active h: (upd - vmean_seg) @ WOT_seg
__global__ __launch_bounds__(256)
void wo_apply_kernel() {
    __shared__ int su[8];
    __shared__ float sdelta[8][Eq];
    int row = blockIdx.x;            // b*2048 + l
    int b = row >> 11;
    int l = row & 2047;
    int t = threadIdx.x;
    if (t < 8) su[t] = g_selmap[(b * 8 + t) * Lq + l];
    __syncthreads();
    bool any = su[0] >= 0 || su[1] >= 0 || su[2] >= 0 || su[3] >= 0 ||
               su[4] >= 0 || su[5] >= 0 || su[6] >= 0 || su[7] >= 0;
    float acc = g_ybase[b * DMq + t];
    if (any) {
        int h = t >> 5, e = t & 31;
        int u = su[h];
        sdelta[h][e] = (u >= 0)
            ? g_upd[(((size_t)(b * 8 + h)) * Uq + u) * Eq + e] - g_vmean[b * DMq + h * 32 + e]
            : 0.f;
        __syncthreads();
        #pragma unroll
        for (int h2 = 0; h2 < 8; h2++) {
            if (su[h2] >= 0) {
                #pragma unroll
                for (int e2 = 0; e2 < 32; e2++)
                    acc += sdelta[h2][e2] * g_wot[(h2 * 32 + e2) * DMq + t];
            }
        }
    }
    g_tmp[(size_t)row * DMq + t] = acc;
}

// ---------------- fused: LN1(x+tmp) -> FFN -> +res -> LN2, + bf16 split --------
__global__ __launch_bounds__(256)
void post_kernel(const float* __restrict__ c1w,
                 const float* __restrict__ c1b,
                 const float* __restrict__ c2w,
                 const float* __restrict__ c2b,
                 const float* __restrict__ g1,
                 const float* __restrict__ b1,
                 const float* __restrict__ g2,
                 const float* __restrict__ b2) {
    __shared__ float s8[8];
    __shared__ float xs[DMq];
    __shared__ float ys[INTERq];
    int row = blockIdx.x;
    int d = threadIdx.x;
    int lane = d & 31, wid = d >> 5;
    size_t off = (size_t)row * DMq + d;
    float v = g_x[off] + g_tmp[off];
    float m = bsum256(v, s8, lane, wid) * (1.0f / (float)DMq);
    float c = v - m;
    float var = bsum256(c * c, s8, lane, wid) * (1.0f / (float)DMq);
    float x1 = c * rsqrtf(var + 1e-5f) * g1[d] + b1[d];
    xs[d] = x1;
    __syncthreads();
    // FFN layer 1: 16 threads per inter unit
    int f = d >> 4, kc = d & 15;
    const float4* w4 = (const float4*)(c1w + (size_t)f * DMq + kc * 16);
    float p = 0.f;
    #pragma unroll
    for (int i = 0; i < 4; i++) {
        float4 wv = w4[i];
        int k0 = kc * 16 + i * 4;
        p += xs[k0]*wv.x + xs[k0+1]*wv.y + xs[k0+2]*wv.z + xs[k0+3]*wv.w;
    }
    p += __shfl_down_sync(0xffffffffu, p, 8);
    p += __shfl_down_sync(0xffffffffu, p, 4);
    p += __shfl_down_sync(0xffffffffu, p, 2);
    p += __shfl_down_sync(0xffffffffu, p, 1);
    if (kc == 0) ys[f] = fmaxf(p + c1b[f], 0.f);
    __syncthreads();
    float a2 = c2b[d];
    const float* w2 = c2w + (size_t)d * INTERq;
    #pragma unroll
    for (int ff = 0; ff < INTERq; ff++) a2 += ys[ff] * w2[ff];
    float v2 = x1 + a2;
    float m2 = bsum256(v2, s8, lane, wid) * (1.0f / (float)DMq);
    float c2 = v2 - m2;
    float var2 = bsum256(c2 * c2, s8, lane, wid) * (1.0f / (float)DMq);
    float xo = c2 * rsqrtf(var2 + 1e-5f) * g2[d] + b2[d];
    g_x[off] = xo;
    __nv_bfloat16 h = __float2bfloat16(xo);
    g_ahi[off] = h;
    g_alo[off] = __float2bfloat16(xo - __bfloat162float(h));
}

// ---------------- batchnorm stats (256 chunks of 32 rows) ----------------------
__global__ void bn_part_kernel() {
    int chunk = blockIdx.x;
    int d = threadIdx.x;
    float s = 0.f, s2 = 0.f;
    int r0 = chunk * 32;
    for (int r = 0; r < 32; r++) {
        float v = g_tmp[(size_t)(r0 + r) * DMq + d];
        s += v; s2 += v * v;
    }
    g_bnp1[chunk * DMq + d] = s;
    g_bnp2[chunk * DMq + d] = s2;
}

__global__ void bn_final_kernel() {
    int d = threadIdx.x;
    float s = 0.f, s2 = 0.f;
    for (int c = 0; c < 256; c++) {
        s  += g_bnp1[c * DMq + d];
        s2 += g_bnp2[c * DMq + d];
    }
    float m = s * (1.0f / (float)BLq);
    g_bnm[d] = m;
    g_bnv[d] = s2 * (1.0f / (float)BLq) - m * m;
}

__global__ void bn_elu_kernel(const float* __restrict__ gam,
                              const float* __restrict__ bet) {
    int t = blockIdx.x * blockDim.x + threadIdx.x;
    if (t >= BLq * DMq) return;
    int d = t % DMq;
    float y = (g_tmp[t] - g_bnm[d]) * rsqrtf(g_bnv[d] + 1e-5f) * gam[d] + bet[d];
    float xo = (y > 0.f) ? y : expm1f(y);
    g_x[t] = xo;
    __nv_bfloat16 h = __float2bfloat16(xo);
    g_ahi[t] = h;
    g_alo[t] = __float2bfloat16(xo - __bfloat162float(h));
}

// ---------------- final LayerNorm into d_out -----------------------------------
__global__ __launch_bounds__(256)
void final_ln_kernel(const float* __restrict__ gam,
                     const float* __restrict__ bet,
                     float* __restrict__ out) {
    __shared__ float s8[8];
    int row = blockIdx.x;
    int d = threadIdx.x;
    int lane = d & 31, wid = d >> 5;
    size_t off = (size_t)row * DMq + d;
    float v = g_x[off];
    float m = bsum256(v, s8, lane, wid) * (1.0f / (float)DMq);
    float c = v - m;
    float var = bsum256(c * c, s8, lane, wid) * (1.0f / (float)DMq);
    out[off] = c * rsqrtf(var + 1e-5f) * gam[d] + bet[d];
}

// ---------------- host driver --------------------------------------------------
extern "C" void kernel_launch(void* const* d_in, const int* in_sizes, int n_in,
                              void* d_out, int out_size) {
    const float* x_in = (const float*)d_in[0];
    const float* wq   = (const float*)d_in[1];
    const float* bq   = (const float*)d_in[2];
    const float* wk   = (const float*)d_in[3];
    const float* bk   = (const float*)d_in[4];
    const float* wv   = (const float*)d_in[5];
    const float* bv   = (const float*)d_in[6];
    const float* wo   = (const float*)d_in[7];
    const float* bo   = (const float*)d_in[8];
    const float* c1w  = (const float*)d_in[9];
    const float* c1b  = (const float*)d_in[10];
    const float* c2w  = (const float*)d_in[11];
    const float* c2b  = (const float*)d_in[12];
    const float* ln1g = (const float*)d_in[13];
    const float* ln1b = (const float*)d_in[14];
    const float* ln2g = (const float*)d_in[15];
    const float* ln2b = (const float*)d_in[16];
    const float* dcw  = (const float*)d_in[17];
    const float* dcb  = (const float*)d_in[18];
    const float* bng  = (const float*)d_in[19];
    const float* bnb  = (const float*)d_in[20];
    const float* fng  = (const float*)d_in[21];
    const float* fnb  = (const float*)d_in[22];
    float* out = (float*)d_out;

    // Real device addresses (host-shadow/ATS trap on GB300)
    void *vp;
    cudaGetSymbolAddress(&vp, g_q);   float* pq   = (float*)vp;
    cudaGetSymbolAddress(&vp, g_k);   float* pk   = (float*)vp;
    cudaGetSymbolAddress(&vp, g_v);   float* pv   = (float*)vp;

    copy_x_kernel<<<(BLq * DMq) / 256, 256>>>(x_in);

    int nw = NLq * DMq * DMq;
    split_w_kernel<<<(nw + 255) / 256, 256>>>(wq, 0);
    split_w_kernel<<<(nw + 255) / 256, 256>>>(wk, 1);
    split_w_kernel<<<(nw + 255) / 256, 256>>>(wv, 2);
    int ncw = (NLq - 1) * 3 * DMq * DMq;
    split_cw_kernel<<<(ncw + 255) / 256, 256>>>(dcw);

    dim3 ggrid(DMq / 128, BLq / 128);   // (2, 64)

    for (int lay = 0; lay < NLq; lay++) {
        gemm_bf16_kernel<<<ggrid, 256>>>(lay * 4 + 0, bq + (size_t)lay * DMq, pq);
        gemm_bf16_kernel<<<ggrid, 256>>>(lay * 4 + 1, bk + (size_t)lay * DMq, pk);
        gemm_bf16_kernel<<<ggrid, 256>>>(lay * 4 + 2, bv + (size_t)lay * DMq, pv);

        uint32_t k0, k1, s0, s1;
        tf2x32(0u, 42u, 0u, (uint32_t)lay, k0, k1);
        tf2x32(k0, k1, 0u, 1u, s0, s1);
        rng_idx_kernel<<<(Lq * Uq + 255) / 256, 256>>>(s0, s1);

        compute_M_kernel<<<(Bq * Hq * Lq * 4) / 256, 256>>>();
        topk_kernel<<<Bq * Hq, 512>>>();
        vmean_part_kernel<<<dim3(32, Bq), DMq>>>();
        vmean_final_kernel<<<Bq, DMq>>>();
        attn_kernel<<<Bq * Hq * 8, 256>>>();

        const float* WO = wo + (size_t)lay * DMq * DMq;
        wot_kernel<<<(DMq * DMq) / 256, 256>>>(WO);
        wo_y_kernel<<<dim3(Bq, 8), 256>>>(WO, bo + (size_t)lay * DMq);
        selmap_clear_kernel<<<(Bq * Hq * Lq) / 256, 256>>>();
        selmap_set_kernel<<<(Bq * Hq * Uq + 255) / 256, 256>>>();
        wo_apply_kernel<<<BLq, 256>>>();

        post_kernel<<<BLq, DMq>>>(c1w + (size_t)lay * INTERq * DMq,
                                  c1b + (size_t)lay * INTERq,
                                  c2w + (size_t)lay * DMq * INTERq,
                                  c2b + (size_t)lay * DMq,
                                  ln1g + (size_t)lay * DMq,
                                  ln1b + (size_t)lay * DMq,
                                  ln2g + (size_t)lay * DMq,
                                  ln2b + (size_t)lay * DMq);

        if (lay < NLq - 1) {
            convgemm_bf16_kernel<<<ggrid, 256>>>(lay, dcb + (size_t)lay * DMq);
            bn_part_kernel<<<256, DMq>>>();
            bn_final_kernel<<<1, DMq>>>();
            bn_elu_kernel<<<(BLq * DMq) / 256, 256>>>(
                bng + (size_t)lay * DMq,
                bnb + (size_t)lay * DMq);
        }
    }

    final_ln_kernel<<<BLq, DMq>>>(fng, fnb, out);
}

// round 11
// speedup vs baseline: 5.2534x; 1.0388x over previous
#include <cuda_runtime.h>
#include <cuda_bf16.h>
#include <math.h>
#include <stdint.h>

// Problem constants
#define Bq   4
#define Lq   2048
#define DMq  256
#define Hq   8
#define Eq   32
#define NLq  3
#define INTERq 16
#define Uq   40
#define BLq  (Bq*Lq)     // 8192
#define QB   5

// ---------------- scratch (device globals; no allocation allowed) -------------
__device__ float g_x[BLq*DMq];
__device__ float g_q[BLq*DMq];
__device__ float g_k[BLq*DMq];
__device__ float g_v[BLq*DMq];
__device__ float g_tmp[BLq*DMq];
__device__ __nv_bfloat16 g_ahi[BLq*DMq];
__device__ __nv_bfloat16 g_alo[BLq*DMq];
__device__ __nv_bfloat16 g_whi[12*DMq*DMq];   // [lay*4+slot][n][k]
__device__ __nv_bfloat16 g_wlo[12*DMq*DMq];
__device__ __nv_bfloat16 g_cwhi[6*DMq*DMq];   // [lay*3+t][o][i]
__device__ __nv_bfloat16 g_cwlo[6*DMq*DMq];
__device__ float g_wot[DMq*DMq];              // WO^T for current layer
__device__ float g_ybase[Bq*DMq];             // vmean @ WO^T + bo
__device__ int   g_selmap[Bq*Hq*Lq];          // tag<<12 | u, tag = lay+1
__device__ int   g_idx[Lq*Uq];
__device__ float g_M[Bq*Hq*Lq];
__device__ int   g_top[Bq*Hq*Uq];
__device__ float g_vmean[Bq*DMq];
__device__ float g_vpart[Bq*32*DMq];
__device__ float g_upd[Bq*Hq*Uq*Eq];
__device__ float g_bnp1[256*DMq];
__device__ float g_bnp2[256*DMq];
__device__ float g_bnm[DMq];
__device__ float g_bnv[DMq];

// ---------------- Threefry-2x32 (matches JAX) ---------------------------------
__host__ __device__ inline void tf2x32(uint32_t k0, uint32_t k1,
                                       uint32_t x0, uint32_t x1,
                                       uint32_t& o0, uint32_t& o1) {
    uint32_t ks[3];
    ks[0] = k0; ks[1] = k1; ks[2] = k0 ^ k1 ^ 0x1BD11BDAu;
    x0 += ks[0]; x1 += ks[1];
    const int R0[4] = {13, 15, 26, 6};
    const int R1[4] = {17, 29, 16, 24};
    #pragma unroll
    for (int i = 0; i < 5; i++) {
        #pragma unroll
        for (int j = 0; j < 4; j++) {
            int r = (i & 1) ? R1[j] : R0[j];
            x0 += x1;
            x1 = (x1 << r) | (x1 >> (32 - r));
            x1 ^= x0;
        }
        x0 += ks[(i + 1) % 3];
        x1 += ks[(i + 2) % 3] + (uint32_t)(i + 1);
    }
    o0 = x0; o1 = x1;
}

__global__ void rng_idx_kernel(uint32_t s0, uint32_t s1) {
    int f = blockIdx.x * blockDim.x + threadIdx.x;
    if (f < Lq * Uq) {
        uint32_t o0, o1;
        tf2x32(s0, s1, 0u, (uint32_t)f, o0, o1);
        g_idx[f] = (int)((o0 ^ o1) & 2047u);
    }
}

// ---------------- block-sum helper (256 threads) -------------------------------
__device__ __forceinline__ float bsum256(float v, float* s8, int lane, int wid) {
    #pragma unroll
    for (int o = 16; o > 0; o >>= 1) v += __shfl_xor_sync(0xffffffffu, v, o);
    if (lane == 0) s8[wid] = v;
    __syncthreads();
    float r = s8[0] + s8[1] + s8[2] + s8[3] + s8[4] + s8[5] + s8[6] + s8[7];
    __syncthreads();
    return r;
}

// ---------------- copy input x + bf16 split ------------------------------------
__global__ void copy_x_kernel(const float* __restrict__ src) {
    int t = blockIdx.x * blockDim.x + threadIdx.x;
    if (t < BLq * DMq) {
        float v = src[t];
        g_x[t] = v;
        __nv_bfloat16 h = __float2bfloat16(v);
        g_ahi[t] = h;
        g_alo[t] = __float2bfloat16(v - __bfloat162float(h));
    }
}

__global__ void split_w_kernel(const float* __restrict__ src, int slot) {
    int t = blockIdx.x * blockDim.x + threadIdx.x;
    if (t < NLq * DMq * DMq) {
        int lay = t >> 16;
        int r = t & 65535;
        float v = src[t];
        __nv_bfloat16 h = __float2bfloat16(v);
        int d = (((lay << 2) + slot) << 16) | r;
        g_whi[d] = h;
        g_wlo[d] = __float2bfloat16(v - __bfloat162float(h));
    }
}

__global__ void split_cw_kernel(const float* __restrict__ dcw) {
    int t = blockIdx.x * blockDim.x + threadIdx.x;
    if (t < (NLq - 1) * 3 * DMq * DMq) {
        int lay = t / (3 * 65536);
        int rem = t % (3 * 65536);
        int tap = rem >> 16;
        int oi = rem & 65535;
        int o = oi >> 8;
        int i = oi & 255;
        float v = dcw[(size_t)lay * 3 * 65536 + o * 768 + i * 3 + tap];
        __nv_bfloat16 h = __float2bfloat16(v);
        g_cwhi[t] = h;
        g_cwlo[t] = __float2bfloat16(v - __bfloat162float(h));
    }
}

// ---------------- split-bf16 tensor-core GEMM ----------------------------------
#define MMA_BF16(c, a, b) \
    asm volatile("mma.sync.aligned.m16n8k16.row.col.f32.bf16.bf16.f32 " \
        "{%0,%1,%2,%3}, {%4,%5,%6,%7}, {%8,%9}, {%0,%1,%2,%3};" \
        : "+f"((c)[0]), "+f"((c)[1]), "+f"((c)[2]), "+f"((c)[3]) \
        : "r"((a)[0]), "r"((a)[1]), "r"((a)[2]), "r"((a)[3]), \
          "r"((b)[0]), "r"((b)[1]))

// fused QKV: grid (2, 64, 3), 256 threads; ping-pong smem, 1 sync/chunk
__global__ __launch_bounds__(256)
void gemm_qkv_kernel(int lay,
                     const float* __restrict__ bq,
                     const float* __restrict__ bk,
                     const float* __restrict__ bv,
                     float* __restrict__ Cq,
                     float* __restrict__ Ck,
                     float* __restrict__ Cv) {
    __shared__ __nv_bfloat16 sAh[2][128*24], sAl[2][128*24];
    __shared__ __nv_bfloat16 sBh[2][128*24], sBl[2][128*24];
    int z = blockIdx.z;
    int slot = lay * 4 + z;
    const float* bias = (z == 0) ? bq : (z == 1) ? bk : bv;
    float* C = (z == 0) ? Cq : (z == 1) ? Ck : Cv;

    int tid = threadIdx.x;
    int m0 = blockIdx.y * 128, n0 = blockIdx.x * 128;
    int lr = tid >> 1, lh = tid & 1;
    int w = tid >> 5, lane = tid & 31;
    int wm = w & 1, wn = w >> 1;
    int grp = lane >> 2, tig = lane & 3;

    const __nv_bfloat16* Wh = g_whi + (size_t)slot * DMq * DMq;
    const __nv_bfloat16* Wl = g_wlo + (size_t)slot * DMq * DMq;
    size_t aoff = (size_t)(m0 + lr) * DMq + lh * 8;
    size_t boff = (size_t)(n0 + lr) * DMq + lh * 8;
    int sidx = lr * 24 + lh * 8;

    float acc[4][4][4];
    #pragma unroll
    for (int i = 0; i < 4; i++)
        #pragma unroll
        for (int j = 0; j < 4; j++)
            #pragma unroll
            for (int q = 0; q < 4; q++) acc[i][j][q] = 0.f;

    uint4 rah = *(const uint4*)(g_ahi + aoff);
    uint4 ral = *(const uint4*)(g_alo + aoff);
    uint4 rbh = *(const uint4*)(Wh + boff);
    uint4 rbl = *(const uint4*)(Wl + boff);

    for (int c = 0; c < 16; c++) {
        int p = c & 1;
        *(uint4*)(sAh[p] + sidx) = rah;
        *(uint4*)(sAl[p] + sidx) = ral;
        *(uint4*)(sBh[p] + sidx) = rbh;
        *(uint4*)(sBl[p] + sidx) = rbl;
        __syncthreads();
        if (c + 1 < 16) {
            rah = *(const uint4*)(g_ahi + aoff + (c + 1) * 16);
            ral = *(const uint4*)(g_alo + aoff + (c + 1) * 16);
            rbh = *(const uint4*)(Wh + boff + (c + 1) * 16);
            rbl = *(const uint4*)(Wl + boff + (c + 1) * 16);
        }
        uint32_t bh[4][2], bl[4][2];
        #pragma unroll
        for (int nf = 0; nf < 4; nf++) {
            int n = wn * 32 + nf * 8 + grp;
            bh[nf][0] = *(const uint32_t*)(sBh[p] + n * 24 + tig * 2);
            bh[nf][1] = *(const uint32_t*)(sBh[p] + n * 24 + tig * 2 + 8);
            bl[nf][0] = *(const uint32_t*)(sBl[p] + n * 24 + tig * 2);
            bl[nf][1] = *(const uint32_t*)(sBl[p] + n * 24 + tig * 2 + 8);
        }
        #pragma unroll
        for (int mf = 0; mf < 4; mf++) {
            int r = wm * 64 + mf * 16 + grp;
            uint32_t ah[4], al[4];
            ah[0] = *(const uint32_t*)(sAh[p] + r * 24 + tig * 2);
            ah[1] = *(const uint32_t*)(sAh[p] + (r + 8) * 24 + tig * 2);
            ah[2] = *(const uint32_t*)(sAh[p] + r * 24 + tig * 2 + 8);
            ah[3] = *(const uint32_t*)(sAh[p] + (r + 8) * 24 + tig * 2 + 8);
            al[0] = *(const uint32_t*)(sAl[p] + r * 24 + tig * 2);
            al[1] = *(const uint32_t*)(sAl[p] + (r + 8) * 24 + tig * 2);
            al[2] = *(const uint32_t*)(sAl[p] + r * 24 + tig * 2 + 8);
            al[3] = *(const uint32_t*)(sAl[p] + (r + 8) * 24 + tig * 2 + 8);
            #pragma unroll
            for (int nf = 0; nf < 4; nf++) {
                MMA_BF16(acc[mf][nf], ah, bh[nf]);
                MMA_BF16(acc[mf][nf], ah, bl[nf]);
                MMA_BF16(acc[mf][nf], al, bh[nf]);
            }
        }
    }

    #pragma unroll
    for (int mf = 0; mf < 4; mf++) {
        int r0 = m0 + wm * 64 + mf * 16 + grp;
        #pragma unroll
        for (int nf = 0; nf < 4; nf++) {
            int c0 = n0 + wn * 32 + nf * 8 + tig * 2;
            float2 v0 = {acc[mf][nf][0] + bias[c0], acc[mf][nf][1] + bias[c0 + 1]};
            float2 v1 = {acc[mf][nf][2] + bias[c0], acc[mf][nf][3] + bias[c0 + 1]};
            *(float2*)&C[(size_t)r0 * DMq + c0] = v0;
            *(float2*)&C[(size_t)(r0 + 8) * DMq + c0] = v1;
        }
    }
}

// ---------------- conv as 3-tap split-bf16 GEMM (ping-pong) --------------------
__global__ __launch_bounds__(256)
void convgemm_bf16_kernel(int lay, const float* __restrict__ cb) {
    __shared__ __nv_bfloat16 sAh[2][128*24], sAl[2][128*24];
    __shared__ __nv_bfloat16 sBh[2][128*24], sBl[2][128*24];
    int tid = threadIdx.x;
    int m0 = blockIdx.y * 128, n0 = blockIdx.x * 128;
    int lr = tid >> 1, lh = tid & 1;
    int w = tid >> 5, lane = tid & 31;
    int wm = w & 1, wn = w >> 1;
    int grp = lane >> 2, tig = lane & 3;

    int m = m0 + lr;
    int b = m >> 11;
    int l = m & 2047;
    size_t aoff[3];
    #pragma unroll
    for (int t = 0; t < 3; t++)
        aoff[t] = (size_t)((b << 11) | ((l + t + 2047) & 2047)) * DMq + lh * 8;
    const __nv_bfloat16* Wh3 = g_cwhi + (size_t)(lay * 3) * DMq * DMq;
    const __nv_bfloat16* Wl3 = g_cwlo + (size_t)(lay * 3) * DMq * DMq;
    size_t boff = (size_t)(n0 + lr) * DMq + lh * 8;
    int sidx = lr * 24 + lh * 8;

    float acc[4][4][4];
    #pragma unroll
    for (int i = 0; i < 4; i++)
        #pragma unroll
        for (int j = 0; j < 4; j++)
            #pragma unroll
            for (int q = 0; q < 4; q++) acc[i][j][q] = 0.f;

    uint4 rah = *(const uint4*)(g_ahi + aoff[0]);
    uint4 ral = *(const uint4*)(g_alo + aoff[0]);
    uint4 rbh = *(const uint4*)(Wh3 + boff);
    uint4 rbl = *(const uint4*)(Wl3 + boff);

    for (int kt = 0; kt < 48; kt++) {
        int p = kt & 1;
        *(uint4*)(sAh[p] + sidx) = rah;
        *(uint4*)(sAl[p] + sidx) = ral;
        *(uint4*)(sBh[p] + sidx) = rbh;
        *(uint4*)(sBl[p] + sidx) = rbl;
        __syncthreads();
        if (kt + 1 < 48) {
            int t2 = (kt + 1) >> 4;
            int c2 = ((kt + 1) & 15) * 16;
            rah = *(const uint4*)(g_ahi + aoff[t2] + c2);
            ral = *(const uint4*)(g_alo + aoff[t2] + c2);
            rbh = *(const uint4*)(Wh3 + (size_t)t2 * DMq * DMq + boff + c2);
            rbl = *(const uint4*)(Wl3 + (size_t)t2 * DMq * DMq + boff + c2);
        }
        uint32_t bh[4][2], bl[4][2];
        #pragma unroll
        for (int nf = 0; nf < 4; nf++) {
            int n = wn * 32 + nf * 8 + grp;
            bh[nf][0] = *(const uint32_t*)(sBh[p] + n * 24 + tig * 2);
            bh[nf][1] = *(const uint32_t*)(sBh[p] + n * 24 + tig * 2 + 8);
            bl[nf][0] = *(const uint32_t*)(sBl[p] + n * 24 + tig * 2);
            bl[nf][1] = *(const uint32_t*)(sBl[p] + n * 24 + tig * 2 + 8);
        }
        #pragma unroll
        for (int mf = 0; mf < 4; mf++) {
            int r = wm * 64 + mf * 16 + grp;
            uint32_t ah[4], al[4];
            ah[0] = *(const uint32_t*)(sAh[p] + r * 24 + tig * 2);
            ah[1] = *(const uint32_t*)(sAh[p] + (r + 8) * 24 + tig * 2);
            ah[2] = *(const uint32_t*)(sAh[p] + r * 24 + tig * 2 + 8);
            ah[3] = *(const uint32_t*)(sAh[p] + (r + 8) * 24 + tig * 2 + 8);
            al[0] = *(const uint32_t*)(sAl[p] + r * 24 + tig * 2);
            al[1] = *(const uint32_t*)(sAl[p] + (r + 8) * 24 + tig * 2);
            al[2] = *(const uint32_t*)(sAl[p] + r * 24 + tig * 2 + 8);
            al[3] = *(const uint32_t*)(sAl[p] + (r + 8) * 24 + tig * 2 + 8);
            #pragma unroll
            for (int nf = 0; nf < 4; nf++) {
                MMA_BF16(acc[mf][nf], ah, bh[nf]);
                MMA_BF16(acc[mf][nf], ah, bl[nf]);
                MMA_BF16(acc[mf][nf], al, bh[nf]);
            }
        }
    }

    #pragma unroll
    for (int mf = 0; mf < 4; mf++) {
        int r0 = m0 + wm * 64 + mf * 16 + grp;
        #pragma unroll
        for (int nf = 0; nf < 4; nf++) {
            int c0 = n0 + wn * 32 + nf * 8 + tig * 2;
            float2 v0 = {acc[mf][nf][0] + cb[c0], acc[mf][nf][1] + cb[c0 + 1]};
            float2 v1 = {acc[mf][nf][2] + cb[c0], acc[mf][nf][3] + cb[c0 + 1]};
            *(float2*)&g_tmp[(size_t)r0 * DMq + c0] = v0;
            *(float2*)&g_tmp[(size_t)(r0 + 8) * DMq + c0] = v1;
        }
    }
}

// ---------------- M: 4 threads per query ---------------------------------------
__global__ void compute_M_kernel() {
    int t = blockIdx.x * blockDim.x + threadIdx.x;
    int q = t >> 2;
    int j = t & 3;
    int l = q & (Lq - 1);
    int bh = q >> 11;
    int h = bh & (Hq - 1);
    int b = bh >> 3;
    const float4* qp = (const float4*)(g_q + ((size_t)(b * Lq + l) * DMq + h * Eq + j * 8));
    float4 q0 = qp[0], q1 = qp[1];
    float mx = -INFINITY, sm = 0.f;
    #pragma unroll 4
    for (int s = 0; s < Uq; s++) {
        int kl = g_idx[l * Uq + s];
        const float4* kp = (const float4*)(g_k + ((size_t)(b * Lq + kl) * DMq + h * Eq + j * 8));
        float4 k0 = kp[0], k1 = kp[1];
        float d = q0.x*k0.x + q0.y*k0.y + q0.z*k0.z + q0.w*k0.w
                + q1.x*k1.x + q1.y*k1.y + q1.z*k1.z + q1.w*k1.w;
        d += __shfl_xor_sync(0xffffffffu, d, 1);
        d += __shfl_xor_sync(0xffffffffu, d, 2);
        mx = fmaxf(mx, d);
        sm += d;
    }
    if (j == 0) g_M[q] = mx - sm * (1.0f / (float)Lq);
}

// ---------------- top-k via full bitonic sort ----------------------------------
__device__ inline uint32_t fsortable(float f) {
    uint32_t u = __float_as_uint(f);
    return (u & 0x80000000u) ? ~u : (u | 0x80000000u);
}

__global__ __launch_bounds__(512)
void topk_kernel() {
    __shared__ unsigned long long key[Lq];
    int bh = blockIdx.x;
    int tid = threadIdx.x;
    const float* Mrow = g_M + (size_t)bh * Lq;
    for (int i = tid; i < Lq; i += 512) {
        uint32_t s = fsortable(Mrow[i]);
        key[i] = ((unsigned long long)(~s) << 32) | (uint32_t)i;
    }
    for (int k = 2; k <= Lq; k <<= 1) {
        for (int j = k >> 1; j > 0; j >>= 1) {
            __syncthreads();
            for (int i = tid; i < Lq; i += 512) {
                int l = i ^ j;
                if (l > i) {
                    unsigned long long a = key[i], c = key[l];
                    bool asc = ((i & k) == 0);
                    if ((a > c) == asc) { key[i] = c; key[l] = a; }
                }
            }
        }
    }
    __syncthreads();
    if (tid < Uq) g_top[bh * Uq + tid] = (int)(key[tid] & 0xffffffffu);
}

// ---------------- mean of v over L: two-stage ----------------------------------
__global__ void vmean_part_kernel() {
    int b = blockIdx.y;
    int chunk = blockIdx.x;
    int d = threadIdx.x;
    float s = 0.f;
    int r0 = chunk * 64;
    for (int r = 0; r < 64; r++)
        s += g_v[(size_t)(b * Lq + r0 + r) * DMq + d];
    g_vpart[(size_t)(b * 32 + chunk) * DMq + d] = s;
}

__global__ void vmean_final_kernel() {
    int b = blockIdx.x;
    int d = threadIdx.x;
    float s = 0.f;
    for (int c = 0; c < 32; c++) s += g_vpart[(size_t)(b * 32 + c) * DMq + d];
    g_vmean[b * DMq + d] = s * (1.0f / (float)Lq);
}

// ---------------- attention: QB queries per block ------------------------------
__global__ __launch_bounds__(256)
void attn_kernel() {
    __shared__ float sp[QB][Lq];
    __shared__ float qs[QB][Eq];
    __shared__ float redm[QB][8];
    __shared__ float reds[QB][8];
    __shared__ float outacc[8][QB][Eq];
    const float SCALE = 0.17677669529663687f;
    int blk = blockIdx.x;
    int grp = blk & 7;
    int bh = blk >> 3;
    int h = bh & (Hq - 1);
    int b = bh >> 3;
    int tid = threadIdx.x;
    int lane = tid & 31;
    int wid = tid >> 5;

    for (int i = tid; i < QB * Eq; i += 256) {
        int qq = i >> 5, e = i & 31;
        int lqi = g_top[bh * Uq + grp * QB + qq];
        qs[qq][e] = g_q[(size_t)(b * Lq + lqi) * DMq + h * Eq + e];
    }
    __syncthreads();

    float lmax[QB];
    #pragma unroll
    for (int qq = 0; qq < QB; qq++) lmax[qq] = -INFINITY;
    for (int kk = tid; kk < Lq; kk += 256) {
        const float4* k4 = (const float4*)(g_k + ((size_t)(b * Lq + kk) * DMq + h * Eq));
        float4 kv[8];
        #pragma unroll
        for (int j = 0; j < 8; j++) kv[j] = k4[j];
        #pragma unroll
        for (int qq = 0; qq < QB; qq++) {
            const float4* q4 = (const float4*)qs[qq];
            float d = 0.f;
            #pragma unroll
            for (int j = 0; j < 8; j++) {
                float4 qv = q4[j];
                d += qv.x*kv[j].x + qv.y*kv[j].y + qv.z*kv[j].z + qv.w*kv[j].w;
            }
            d *= SCALE;
            sp[qq][kk] = d;
            lmax[qq] = fmaxf(lmax[qq], d);
        }
    }
    #pragma unroll
    for (int qq = 0; qq < QB; qq++) {
        float v = lmax[qq];
        #pragma unroll
        for (int off = 16; off > 0; off >>= 1)
            v = fmaxf(v, __shfl_xor_sync(0xffffffffu, v, off));
        if (lane == 0) redm[qq][wid] = v;
    }
    __syncthreads();
    float gmax[QB];
    #pragma unroll
    for (int qq = 0; qq < QB; qq++) {
        float v = redm[qq][0];
        #pragma unroll
        for (int w2 = 1; w2 < 8; w2++) v = fmaxf(v, redm[qq][w2]);
        gmax[qq] = v;
    }

    float lsum[QB];
    #pragma unroll
    for (int qq = 0; qq < QB; qq++) lsum[qq] = 0.f;
    for (int kk = tid; kk < Lq; kk += 256) {
        #pragma unroll
        for (int qq = 0; qq < QB; qq++) {
            float p = expf(sp[qq][kk] - gmax[qq]);
            sp[qq][kk] = p;
            lsum[qq] += p;
        }
    }
    #pragma unroll
    for (int qq = 0; qq < QB; qq++) {
        float v = lsum[qq];
        #pragma unroll
        for (int off = 16; off > 0; off >>= 1)
            v += __shfl_xor_sync(0xffffffffu, v, off);
        if (lane == 0) reds[qq][wid] = v;
    }
    __syncthreads();
    float ginv[QB];
    #pragma unroll
    for (int qq = 0; qq < QB; qq++) {
        float v = 0.f;
        #pragma unroll
        for (int w2 = 0; w2 < 8; w2++) v += reds[qq][w2];
        ginv[qq] = 1.0f / v;
    }

    {
        int e = lane;
        float acc[QB];
        #pragma unroll
        for (int qq = 0; qq < QB; qq++) acc[qq] = 0.f;
        for (int kk = wid; kk < Lq; kk += 8) {
            float vv = g_v[(size_t)(b * Lq + kk) * DMq + h * Eq + e];
            #pragma unroll
            for (int qq = 0; qq < QB; qq++)
                acc[qq] += sp[qq][kk] * vv;
        }
        #pragma unroll
        for (int qq = 0; qq < QB; qq++) outacc[wid][qq][e] = acc[qq];
    }
    __syncthreads();
    if (tid < QB * Eq) {
        int qq = tid >> 5, e = tid & 31;
        float s = 0.f;
        #pragma unroll
        for (int w2 = 0; w2 < 8; w2++) s += outacc[w2][qq][e];
        g_upd[((size_t)bh * Uq + grp * QB + qq) * Eq + e] = s * ginv[qq];
    }
}

// ---------------- WO prep: wot transpose + ybase + selmap set (one launch) -----
// grid: 256 (wot) + 32 (wo_y) + 5 (selmap_set) = 293 blocks, 256 threads
__global__ __launch_bounds__(256)
void wo_prep_kernel(int lay, const float* __restrict__ WO,
                    const float* __restrict__ bo) {
    int bid = blockIdx.x;
    int tid = threadIdx.x;
    if (bid < 256) {
        int t = bid * 256 + tid;           // t = d*256+n
        int d = t >> 8, n = t & 255;
        g_wot[t] = WO[n * DMq + d];
    } else if (bid < 288) {
        __shared__ float vm[DMq];
        int q = bid - 256;
        int b = q >> 3, ng = q & 7;
        vm[tid] = g_vmean[b * DMq + tid];
        __syncthreads();
        int nl = tid >> 3, dc = tid & 7;
        int n = ng * 32 + nl;
        const float4* w4 = (const float4*)(WO + (size_t)n * DMq + dc * 32);
        float s = 0.f;
        #pragma unroll
        for (int i = 0; i < 8; i++) {
            float4 wv = w4[i];
            int d0 = dc * 32 + i * 4;
            s += vm[d0]*wv.x + vm[d0+1]*wv.y + vm[d0+2]*wv.z + vm[d0+3]*wv.w;
        }
        s += __shfl_down_sync(0xffffffffu, s, 4);
        s += __shfl_down_sync(0xffffffffu, s, 2);
        s += __shfl_down_sync(0xffffffffu, s, 1);
        if (dc == 0) g_ybase[b * DMq + n] = s + bo[n];
    } else {
        int t = (bid - 288) * 256 + tid;   // B*H*U = 1280
        if (t < Bq * Hq * Uq) {
            int u = t % Uq;
            int bh = t / Uq;
            int l = g_top[t];
            g_selmap[bh * Lq + l] = ((lay + 1) << 12) | u;
        }
    }
}

// out_row(b,l) = y_b + sum over active h: (upd - vmean_seg) @ WOT_seg
__global__ __launch_bounds__(256)
void wo_apply_kernel(int lay) {
    __shared__ int su[8];
    __shared__ float sdelta[8][Eq];
    int row = blockIdx.x;            // b*2048 + l
    int b = row >> 11;
    int l = row & 2047;
    int t = threadIdx.x;
    int tag = (lay + 1) << 12;
    if (t < 8) {
        int v = g_selmap[(b * 8 + t) * Lq + l];
        su[t] = ((v & ~4095) == tag) ? (v & 4095) : -1;
    }
    __syncthreads();
    bool any = su[0] >= 0 || su[1] >= 0 || su[2] >= 0 || su[3] >= 0 ||
               su[4] >= 0 || su[5] >= 0 || su[6] >= 0 || su[7] >= 0;
    float acc = g_ybase[b * DMq + t];
    if (any) {
        int h = t >> 5, e = t & 31;
        int u = su[h];
        sdelta[h][e] = (u >= 0)
            ? g_upd[(((size_t)(b * 8 + h)) * Uq + u) * Eq + e] - g_vmean[b * DMq + h * 32 + e]
            : 0.f;
        __syncthreads();
        #pragma unroll
        for (int h2 = 0; h2 < 8; h2++) {
            if (su[h2] >= 0) {
                #pragma unroll
                for (int e2 = 0; e2 < 32; e2++)
                    acc += sdelta[h2][e2] * g_wot[(h2 * 32 + e2) * DMq + t];
            }
        }
    }
    g_tmp[(size_t)row * DMq + t] = acc;
}

// ---------------- fused: LN1(x+tmp) -> FFN -> +res -> LN2, + bf16 split --------
__global__ __launch_bounds__(256)
void post_kernel(const float* __restrict__ c1w,
                 const float* __restrict__ c1b,
                 const float* __restrict__ c2w,
                 const float* __restrict__ c2b,
                 const float* __restrict__ g1,
                 const float* __restrict__ b1,
                 const float* __restrict__ g2,
                 const float* __restrict__ b2) {
    __shared__ float s8[8];
    __shared__ float xs[DMq];
    __shared__ float ys[INTERq];
    int row = blockIdx.x;
    int d = threadIdx.x;
    int lane = d & 31, wid = d >> 5;
    size_t off = (size_t)row * DMq + d;
    float v = g_x[off] + g_tmp[off];
    float m = bsum256(v, s8, lane, wid) * (1.0f / (float)DMq);
    float c = v - m;
    float var = bsum256(c * c, s8, lane, wid) * (1.0f / (float)DMq);
    float x1 = c * rsqrtf(var + 1e-5f) * g1[d] + b1[d];
    xs[d] = x1;
    __syncthreads();
    int f = d >> 4, kc = d & 15;
    const float4* w4 = (const float4*)(c1w + (size_t)f * DMq + kc * 16);
    float p = 0.f;
    #pragma unroll
    for (int i = 0; i < 4; i++) {
        float4 wv = w4[i];
        int k0 = kc * 16 + i * 4;
        p += xs[k0]*wv.x + xs[k0+1]*wv.y + xs[k0+2]*wv.z + xs[k0+3]*wv.w;
    }
    p += __shfl_down_sync(0xffffffffu, p, 8);
    p += __shfl_down_sync(0xffffffffu, p, 4);
    p += __shfl_down_sync(0xffffffffu, p, 2);
    p += __shfl_down_sync(0xffffffffu, p, 1);
    if (kc == 0) ys[f] = fmaxf(p + c1b[f], 0.f);
    __syncthreads();
    float a2 = c2b[d];
    const float* w2 = c2w + (size_t)d * INTERq;
    #pragma unroll
    for (int ff = 0; ff < INTERq; ff++) a2 += ys[ff] * w2[ff];
    float v2 = x1 + a2;
    float m2 = bsum256(v2, s8, lane, wid) * (1.0f / (float)DMq);
    float c2 = v2 - m2;
    float var2 = bsum256(c2 * c2, s8, lane, wid) * (1.0f / (float)DMq);
    float xo = c2 * rsqrtf(var2 + 1e-5f) * g2[d] + b2[d];
    g_x[off] = xo;
    __nv_bfloat16 h = __float2bfloat16(xo);
    g_ahi[off] = h;
    g_alo[off] = __float2bfloat16(xo - __bfloat162float(h));
}

// ---------------- batchnorm stats (256 chunks of 32 rows) ----------------------
__global__ void bn_part_kernel() {
    int chunk = blockIdx.x;
    int d = threadIdx.x;
    float s = 0.f, s2 = 0.f;
    int r0 = chunk * 32;
    for (int r = 0; r < 32; r++) {
        float v = g_tmp[(size_t)(r0 + r) * DMq + d];
        s += v; s2 += v * v;
    }
    g_bnp1[chunk * DMq + d] = s;
    g_bnp2[chunk * DMq + d] = s2;
}

__global__ void bn_final_kernel() {
    int d = threadIdx.x;
    float s = 0.f, s2 = 0.f;
    for (int c = 0; c < 256; c++) {
        s  += g_bnp1[c * DMq + d];
        s2 += g_bnp2[c * DMq + d];
    }
    float m = s * (1.0f / (float)BLq);
    g_bnm[d] = m;
    g_bnv[d] = s2 * (1.0f / (float)BLq) - m * m;
}

__global__ void bn_elu_kernel(const float* __restrict__ gam,
                              const float* __restrict__ bet) {
    int t = blockIdx.x * blockDim.x + threadIdx.x;
    if (t >= BLq * DMq) return;
    int d = t % DMq;
    float y = (g_tmp[t] - g_bnm[d]) * rsqrtf(g_bnv[d] + 1e-5f) * gam[d] + bet[d];
    float xo = (y > 0.f) ? y : expm1f(y);
    g_x[t] = xo;
    __nv_bfloat16 h = __float2bfloat16(xo);
    g_ahi[t] = h;
    g_alo[t] = __float2bfloat16(xo - __bfloat162float(h));
}

// ---------------- final LayerNorm into d_out -----------------------------------
__global__ __launch_bounds__(256)
void final_ln_kernel(const float* __restrict__ gam,
                     const float* __restrict__ bet,
                     float* __restrict__ out) {
    __shared__ float s8[8];
    int row = blockIdx.x;
    int d = threadIdx.x;
    int lane = d & 31, wid = d >> 5;
    size_t off = (size_t)row * DMq + d;
    float v = g_x[off];
    float m = bsum256(v, s8, lane, wid) * (1.0f / (float)DMq);
    float c = v - m;
    float var = bsum256(c * c, s8, lane, wid) * (1.0f / (float)DMq);
    out[off] = c * rsqrtf(var + 1e-5f) * gam[d] + bet[d];
}

// ---------------- host driver --------------------------------------------------
extern "C" void kernel_launch(void* const* d_in, const int* in_sizes, int n_in,
                              void* d_out, int out_size) {
    const float* x_in = (const float*)d_in[0];
    const float* wq   = (const float*)d_in[1];
    const float* bq   = (const float*)d_in[2];
    const float* wk   = (const float*)d_in[3];
    const float* bk   = (const float*)d_in[4];
    const float* wv   = (const float*)d_in[5];
    const float* bv   = (const float*)d_in[6];
    const float* wo   = (const float*)d_in[7];
    const float* bo   = (const float*)d_in[8];
    const float* c1w  = (const float*)d_in[9];
    const float* c1b  = (const float*)d_in[10];
    const float* c2w  = (const float*)d_in[11];
    const float* c2b  = (const float*)d_in[12];
    const float* ln1g = (const float*)d_in[13];
    const float* ln1b = (const float*)d_in[14];
    const float* ln2g = (const float*)d_in[15];
    const float* ln2b = (const float*)d_in[16];
    const float* dcw  = (const float*)d_in[17];
    const float* dcb  = (const float*)d_in[18];
    const float* bng  = (const float*)d_in[19];
    const float* bnb  = (const float*)d_in[20];
    const float* fng  = (const float*)d_in[21];
    const float* fnb  = (const float*)d_in[22];
    float* out = (float*)d_out;

    // Real device addresses (host-shadow/ATS trap on GB300)
    void *vp;
    cudaGetSymbolAddress(&vp, g_q);   float* pq   = (float*)vp;
    cudaGetSymbolAddress(&vp, g_k);   float* pk   = (float*)vp;
    cudaGetSymbolAddress(&vp, g_v);   float* pv   = (float*)vp;

    copy_x_kernel<<<(BLq * DMq) / 256, 256>>>(x_in);

    int nw = NLq * DMq * DMq;
    split_w_kernel<<<(nw + 255) / 256, 256>>>(wq, 0);
    split_w_kernel<<<(nw + 255) / 256, 256>>>(wk, 1);
    split_w_kernel<<<(nw + 255) / 256, 256>>>(wv, 2);
    int ncw = (NLq - 1) * 3 * DMq * DMq;
    split_cw_kernel<<<(ncw + 255) / 256, 256>>>(dcw);

    dim3 qkvgrid(DMq / 128, BLq / 128, 3);   // (2, 64, 3)
    dim3 cgrid(DMq / 128, BLq / 128);        // (2, 64)

    for (int lay = 0; lay < NLq; lay++) {
        gemm_qkv_kernel<<<qkvgrid, 256>>>(lay,
            bq + (size_t)lay * DMq, bk + (size_t)lay * DMq, bv + (size_t)lay * DMq,
            pq, pk, pv);

        uint32_t k0, k1, s0, s1;
        tf2x32(0u, 42u, 0u, (uint32_t)lay, k0, k1);
        tf2x32(k0, k1, 0u, 1u, s0, s1);
        rng_idx_kernel<<<(Lq * Uq + 255) / 256, 256>>>(s0, s1);

        compute_M_kernel<<<(Bq * Hq * Lq * 4) / 256, 256>>>();
        topk_kernel<<<Bq * Hq, 512>>>();
        vmean_part_kernel<<<dim3(32, Bq), DMq>>>();
        vmean_final_kernel<<<Bq, DMq>>>();

        const float* WO = wo + (size_t)lay * DMq * DMq;
        wo_prep_kernel<<<293, 256>>>(lay, WO, bo + (size_t)lay * DMq);
        attn_kernel<<<Bq * Hq * 8, 256>>>();
        wo_apply_kernel<<<BLq, 256>>>(lay);

        post_kernel<<<BLq, DMq>>>(c1w + (size_t)lay * INTERq * DMq,
                                  c1b + (size_t)lay * INTERq,
                                  c2w + (size_t)lay * DMq * INTERq,
                                  c2b + (size_t)lay * DMq,
                                  ln1g + (size_t)lay * DMq,
                                  ln1b + (size_t)lay * DMq,
                                  ln2g + (size_t)lay * DMq,
                                  ln2b + (size_t)lay * DMq);

        if (lay < NLq - 1) {
            convgemm_bf16_kernel<<<cgrid, 256>>>(lay, dcb + (size_t)lay * DMq);
            bn_part_kernel<<<256, DMq>>>();
            bn_final_kernel<<<1, DMq>>>();
            bn_elu_kernel<<<(BLq * DMq) / 256, 256>>>(
                bng + (size_t)lay * DMq,
                bnb + (size_t)lay * DMq);
        }
    }

    final_ln_kernel<<<BLq, DMq>>>(fng, fnb, out);
}